// round 3
// baseline (speedup 1.0000x reference)
#include <cuda_runtime.h>
#include <math.h>
#include <stdint.h>

#define B_    4
#define L_    4096
#define H_    1024
#define LC_   1024
#define KSEL_ 512
#define WIN_  256
#define NW_   16
#define SCALE_ 0.125f

typedef long long ll;

// ---------------- scratch -----------------------------------------------------
__device__ float g_Q[(size_t)B_ * L_ * H_];
__device__ float g_Kbuf[(size_t)B_ * L_ * H_];
__device__ float g_Vbuf[(size_t)B_ * L_ * H_];
__device__ float g_VT[(size_t)B_ * H_ * L_];
__device__ float g_cmp[(size_t)B_ * LC_ * H_];
__device__ float g_Qc[(size_t)B_ * LC_ * H_];
__device__ float g_Kc[(size_t)B_ * LC_ * H_];
__device__ float g_Vc[(size_t)B_ * LC_ * H_];
__device__ float g_VcT[(size_t)B_ * H_ * LC_];
__device__ float g_S[(size_t)B_ * LC_ * LC_];
__device__ float g_comp_out[(size_t)B_ * LC_ * H_];
__device__ float g_Qs[(size_t)B_ * KSEL_ * H_];
__device__ float g_Ks[(size_t)B_ * KSEL_ * H_];
__device__ float g_Vs[(size_t)B_ * KSEL_ * H_];
__device__ float g_VsT[(size_t)B_ * H_ * KSEL_];
__device__ float g_sel_out[(size_t)B_ * KSEL_ * H_];
__device__ float g_win_out[(size_t)B_ * L_ * H_];
__device__ float g_comb[(size_t)B_ * L_ * 3 * H_];
__device__ float g_pre[(size_t)B_ * L_ * H_];
__device__ float g_gates[(size_t)B_ * L_ * 3];
__device__ float g_scores[(size_t)B_ * L_];
__device__ int   g_idx[B_ * KSEL_];
__device__ float g_WqT[(size_t)H_ * H_];
__device__ float g_WkT[(size_t)H_ * H_];
__device__ float g_WvT[(size_t)H_ * H_];
__device__ float g_WcT[(size_t)4 * H_ * H_];
__device__ float g_WoT[(size_t)3 * H_ * H_];

// ---------------- asm helpers --------------------------------------------------
__device__ __forceinline__ void mma_tf32(float& c0, float& c1, float& c2, float& c3,
                                         uint32_t a0, uint32_t a1, uint32_t a2, uint32_t a3,
                                         uint32_t b0, uint32_t b1) {
    asm volatile(
        "mma.sync.aligned.m16n8k8.row.col.f32.tf32.tf32.f32 "
        "{%0,%1,%2,%3}, {%4,%5,%6,%7}, {%8,%9}, {%0,%1,%2,%3};"
        : "+f"(c0), "+f"(c1), "+f"(c2), "+f"(c3)
        : "r"(a0), "r"(a1), "r"(a2), "r"(a3), "r"(b0), "r"(b1));
}
__device__ __forceinline__ void ldsm4(uint32_t& r0, uint32_t& r1, uint32_t& r2, uint32_t& r3,
                                      uint32_t addr) {
    asm volatile("ldmatrix.sync.aligned.m8n8.x4.shared.b16 {%0,%1,%2,%3}, [%4];"
                 : "=r"(r0), "=r"(r1), "=r"(r2), "=r"(r3) : "r"(addr));
}
__device__ __forceinline__ void cpasync16(uint32_t dst, const float* src) {
    asm volatile("cp.async.cg.shared.global [%0], [%1], 16;" :: "r"(dst), "l"(src));
}
__device__ __forceinline__ void cp_commit() { asm volatile("cp.async.commit_group;"); }
template <int N> __device__ __forceinline__ void cp_wait() {
    asm volatile("cp.async.wait_group %0;" :: "n"(N));
}

// ---------------- tf32 TC GEMM: C = alpha*A*B^T + bias -------------------------
// A: MxK row-major ld=lda. B: NxK row-major ld=ldb. C: MxN row-major.
// Inputs are fp32; HMMA consumes top bits (tf32 truncation).
// batch z: A + (z/inner)*saO + (z%inner)*saI (same for B), C + z*sC.
// REQUIRES M%128==0, N%128==0, K%16==0, K>=48.
#define BK_     16
#define ASTR_   20
#define STG_    4
#define STGF_   (2 * 128 * ASTR_)   // floats per stage (A+B)

__global__ void __launch_bounds__(128)
gemm_tt(const float* __restrict__ A, const float* __restrict__ Bm,
        const float* __restrict__ bias, float* __restrict__ C,
        int M, int N, int K, float alpha, int lda, int ldb,
        ll saO, ll saI, int innerCnt, ll sbO, ll sbI, ll sC)
{
    extern __shared__ float sm[];
    const int z = blockIdx.z;
    const float* Ab = A + (ll)(z / innerCnt) * saO + (ll)(z % innerCnt) * saI
                        + (ll)blockIdx.y * 128 * lda;
    const float* Bb = Bm + (ll)(z / innerCnt) * sbO + (ll)(z % innerCnt) * sbI
                        + (ll)blockIdx.x * 128 * ldb;
    float* Cb = C + (ll)z * sC;

    const int tid = threadIdx.x, lane = tid & 31, warp = tid >> 5;
    const int wm = (warp & 1) * 64, wn = (warp >> 1) * 64;
    const uint32_t smemBase = (uint32_t)__cvta_generic_to_shared(sm);

    const float* aSrc = Ab + (ll)tid * lda;
    const float* bSrc = Bb + (ll)tid * ldb;
    const uint32_t dstA = smemBase + (uint32_t)(tid * ASTR_) * 4u;
    const uint32_t dstB = dstA + 2560u * 4u;

    const int laneRow = lane & 15;
    const int laneCol = (lane >> 4) << 2;
    // fragment smem float-offsets (add slotBase + ks at use)
    int aOff[4], bOff[4];
#pragma unroll
    for (int mt = 0; mt < 4; mt++) aOff[mt] = (wm + mt * 16 + laneRow) * ASTR_ + laneCol;
#pragma unroll
    for (int np = 0; np < 4; np++) bOff[np] = 2560 + (wn + np * 16 + laneRow) * ASTR_ + laneCol;

    float acc[4][8][4];
#pragma unroll
    for (int mt = 0; mt < 4; mt++)
#pragma unroll
        for (int nt = 0; nt < 8; nt++)
#pragma unroll
            for (int i = 0; i < 4; i++) acc[mt][nt][i] = 0.f;

    const int kTiles = K >> 4;

    // prologue: stages 0..STG_-2
#pragma unroll
    for (int s = 0; s < STG_ - 1; s++) {
        const float* a = aSrc + s * BK_;
        const float* b = bSrc + s * BK_;
        const uint32_t da = dstA + (uint32_t)(s * STGF_) * 4u;
        const uint32_t db = dstB + (uint32_t)(s * STGF_) * 4u;
#pragma unroll
        for (int j = 0; j < 4; j++) cpasync16(da + j * 16, a + j * 4);
#pragma unroll
        for (int j = 0; j < 4; j++) cpasync16(db + j * 16, b + j * 4);
        cp_commit();
    }

    for (int kt = 0; kt < kTiles; kt++) {
        cp_wait<STG_ - 2>();
        __syncthreads();

        // issue loads for stage kt+STG_-1 (writes slot (kt-1)%STG_, safe post-sync)
        if (kt + STG_ - 1 < kTiles) {
            const int s = kt + STG_ - 1;
            const int slot = s % STG_;
            const float* a = aSrc + s * BK_;
            const float* b = bSrc + s * BK_;
            const uint32_t da = dstA + (uint32_t)(slot * STGF_) * 4u;
            const uint32_t db = dstB + (uint32_t)(slot * STGF_) * 4u;
#pragma unroll
            for (int j = 0; j < 4; j++) cpasync16(da + j * 16, a + j * 4);
#pragma unroll
            for (int j = 0; j < 4; j++) cpasync16(db + j * 16, b + j * 4);
        }
        cp_commit();   // commit every iter to keep group accounting uniform

        const uint32_t slotB = smemBase + (uint32_t)((kt % STG_) * STGF_) * 4u;
#pragma unroll
        for (int ks = 0; ks < 16; ks += 8) {
            uint32_t afr[4][4], bfr[4][4];
#pragma unroll
            for (int mt = 0; mt < 4; mt++)
                ldsm4(afr[mt][0], afr[mt][1], afr[mt][2], afr[mt][3],
                      slotB + (uint32_t)(aOff[mt] + ks) * 4u);
#pragma unroll
            for (int np = 0; np < 4; np++)
                ldsm4(bfr[np][0], bfr[np][1], bfr[np][2], bfr[np][3],
                      slotB + (uint32_t)(bOff[np] + ks) * 4u);
#pragma unroll
            for (int mt = 0; mt < 4; mt++)
#pragma unroll
                for (int np = 0; np < 4; np++) {
                    mma_tf32(acc[mt][2 * np][0], acc[mt][2 * np][1],
                             acc[mt][2 * np][2], acc[mt][2 * np][3],
                             afr[mt][0], afr[mt][1], afr[mt][2], afr[mt][3],
                             bfr[np][0], bfr[np][2]);
                    mma_tf32(acc[mt][2 * np + 1][0], acc[mt][2 * np + 1][1],
                             acc[mt][2 * np + 1][2], acc[mt][2 * np + 1][3],
                             afr[mt][0], afr[mt][1], afr[mt][2], afr[mt][3],
                             bfr[np][1], bfr[np][3]);
                }
        }
        __syncthreads();
    }

    const int g = lane >> 2, tg = lane & 3;
#pragma unroll
    for (int mt = 0; mt < 4; mt++) {
        const int r0 = blockIdx.y * 128 + wm + mt * 16 + g;
#pragma unroll
        for (int nt = 0; nt < 8; nt++) {
            const int col = blockIdx.x * 128 + wn + nt * 8 + tg * 2;
            float2 bv = make_float2(0.f, 0.f);
            if (bias) bv = *(const float2*)&bias[col];
            float2 o;
            o.x = alpha * acc[mt][nt][0] + bv.x;
            o.y = alpha * acc[mt][nt][1] + bv.y;
            *(float2*)(Cb + (ll)r0 * N + col) = o;
            o.x = alpha * acc[mt][nt][2] + bv.x;
            o.y = alpha * acc[mt][nt][3] + bv.y;
            *(float2*)(Cb + (ll)(r0 + 8) * N + col) = o;
        }
    }
}

// ---------------- batched transpose: out[z][c][r] = in[z][r][c] ---------------
__global__ void transpose_kernel(const float* __restrict__ in, float* __restrict__ out,
                                 int R, int C)
{
    __shared__ float t[32][33];
    const int z = blockIdx.z;
    const float* ib = in + (ll)z * R * C;
    float* ob = out + (ll)z * R * C;
    const int c0 = blockIdx.x * 32, r0 = blockIdx.y * 32;
#pragma unroll
    for (int i = threadIdx.y; i < 32; i += 8)
        t[i][threadIdx.x] = ib[(ll)(r0 + i) * C + c0 + threadIdx.x];
    __syncthreads();
#pragma unroll
    for (int i = threadIdx.y; i < 32; i += 8)
        ob[(ll)(c0 + i) * R + r0 + threadIdx.x] = t[threadIdx.x][i];
}

// ---------------- gates + selection scores ------------------------------------
__global__ void gates_scores_kernel(const float* __restrict__ x,
                                    const float* __restrict__ Wg, const float* __restrict__ bg,
                                    const float* __restrict__ Ws, const float* __restrict__ bs,
                                    float* __restrict__ gates, float* __restrict__ scores)
{
    const int row = blockIdx.x * (blockDim.x >> 5) + (threadIdx.x >> 5);
    const int lane = threadIdx.x & 31;
    if (row >= B_ * L_) return;
    const float* xr = x + (ll)row * H_;
    float a0 = 0.f, a1 = 0.f, a2 = 0.f, a3 = 0.f;
    for (int k = lane; k < H_; k += 32) {
        const float xv = xr[k];
        a0 += xv * Wg[k * 3 + 0];
        a1 += xv * Wg[k * 3 + 1];
        a2 += xv * Wg[k * 3 + 2];
        a3 += xv * Ws[k];
    }
#pragma unroll
    for (int o = 16; o > 0; o >>= 1) {
        a0 += __shfl_down_sync(0xffffffffu, a0, o);
        a1 += __shfl_down_sync(0xffffffffu, a1, o);
        a2 += __shfl_down_sync(0xffffffffu, a2, o);
        a3 += __shfl_down_sync(0xffffffffu, a3, o);
    }
    if (lane == 0) {
        float s0 = 1.f / (1.f + expf(-(a0 + bg[0])));
        float s1 = 1.f / (1.f + expf(-(a1 + bg[1])));
        float s2 = 1.f / (1.f + expf(-(a2 + bg[2])));
        float inv = 1.f / (s0 + s1 + s2 + 1e-6f);
        gates[row * 3 + 0] = s0 * inv;
        gates[row * 3 + 1] = s1 * inv;
        gates[row * 3 + 2] = s2 * inv;
        scores[row] = a3 + bs[0];
    }
}

// ---------------- top-512 per batch ------------------------------------------
__global__ void topk_kernel(const float* __restrict__ scores, int* __restrict__ idx_out)
{
    __shared__ float sv[L_];
    __shared__ int   si[L_];
    __shared__ int   top[KSEL_];
    const int b = blockIdx.x;
    const float* s = scores + (ll)b * L_;
    for (int i = threadIdx.x; i < L_; i += blockDim.x) { sv[i] = s[i]; si[i] = i; }
    __syncthreads();
    for (int k = 2; k <= L_; k <<= 1)
        for (int j = k >> 1; j > 0; j >>= 1) {
            for (int i = threadIdx.x; i < L_; i += blockDim.x) {
                const int ixj = i ^ j;
                if (ixj > i) {
                    const bool desc = ((i & k) == 0);
                    const float a = sv[i], c = sv[ixj];
                    const bool sw = desc ? (a < c) : (a > c);
                    if (sw) {
                        sv[i] = c; sv[ixj] = a;
                        const int t = si[i]; si[i] = si[ixj]; si[ixj] = t;
                    }
                }
            }
            __syncthreads();
        }
    for (int i = threadIdx.x; i < KSEL_; i += blockDim.x) top[i] = si[i];
    __syncthreads();
    for (int k = 2; k <= KSEL_; k <<= 1)
        for (int j = k >> 1; j > 0; j >>= 1) {
            for (int i = threadIdx.x; i < KSEL_; i += blockDim.x) {
                const int ixj = i ^ j;
                if (ixj > i) {
                    const bool asc = ((i & k) == 0);
                    const int a = top[i], c = top[ixj];
                    const bool sw = asc ? (a > c) : (a < c);
                    if (sw) { top[i] = c; top[ixj] = a; }
                }
            }
            __syncthreads();
        }
    for (int i = threadIdx.x; i < KSEL_; i += blockDim.x) idx_out[b * KSEL_ + i] = top[i];
}

// ---------------- gather selected rows ----------------------------------------
__global__ void gather_kernel(const float* __restrict__ Q, const float* __restrict__ K,
                              const float* __restrict__ V, const int* __restrict__ idx,
                              float* __restrict__ Qs, float* __restrict__ Ks, float* __restrict__ Vs)
{
    const int b = blockIdx.y, r = blockIdx.x;
    const int src = idx[b * KSEL_ + r];
    const ll so = ((ll)b * L_ + src) * H_;
    const ll dst = ((ll)b * KSEL_ + r) * H_;
    for (int i = threadIdx.x; i < H_; i += blockDim.x) {
        Qs[dst + i] = Q[so + i];
        Ks[dst + i] = K[so + i];
        Vs[dst + i] = V[so + i];
    }
}

// ---------------- row softmax --------------------------------------------------
__global__ void softmax_kernel(float* __restrict__ S, int n)
{
    const ll row = blockIdx.x;
    float* s = S + row * (ll)n;
    const int tid = threadIdx.x;
    __shared__ float red[32];
    __shared__ float bc;

    float m = -1e30f;
    for (int i = tid; i < n; i += blockDim.x) m = fmaxf(m, s[i]);
#pragma unroll
    for (int o = 16; o > 0; o >>= 1) m = fmaxf(m, __shfl_xor_sync(0xffffffffu, m, o));
    if ((tid & 31) == 0) red[tid >> 5] = m;
    __syncthreads();
    if (tid == 0) {
        float mm = -1e30f;
        for (int i = 0; i < (int)(blockDim.x >> 5); i++) mm = fmaxf(mm, red[i]);
        bc = mm;
    }
    __syncthreads();
    m = bc;
    __syncthreads();

    float sum = 0.f;
    for (int i = tid; i < n; i += blockDim.x) {
        const float e = expf(s[i] - m);
        s[i] = e;
        sum += e;
    }
#pragma unroll
    for (int o = 16; o > 0; o >>= 1) sum += __shfl_xor_sync(0xffffffffu, sum, o);
    if ((tid & 31) == 0) red[tid >> 5] = sum;
    __syncthreads();
    if (tid == 0) {
        float ss = 0.f;
        for (int i = 0; i < (int)(blockDim.x >> 5); i++) ss += red[i];
        bc = 1.f / ss;
    }
    __syncthreads();
    const float inv = bc;
    for (int i = tid; i < n; i += blockDim.x) s[i] *= inv;
}

// ---------------- assemble gated combined -------------------------------------
__global__ void assemble_kernel(const float* __restrict__ comp_out, const float* __restrict__ sel_out,
                                const float* __restrict__ win_out, const float* __restrict__ gates,
                                float* __restrict__ comb)
{
    const ll t = blockIdx.x;
    const int b = (int)(t >> 12), l = (int)(t & 4095);
    const float g0 = gates[t * 3 + 0], g1 = gates[t * 3 + 1], g2 = gates[t * 3 + 2];
    float* c = comb + t * (ll)(3 * H_);
    const float* co = comp_out + ((ll)b * LC_ + l) * H_;
    const float* so = sel_out + ((ll)b * KSEL_ + l) * H_;
    const float* wo = win_out + t * (ll)H_;
    const bool hasC = (l < LC_), hasS = (l < KSEL_);
    for (int i = threadIdx.x; i < H_; i += blockDim.x) {
        c[i]          = hasC ? co[i] * g0 : 0.f;
        c[H_ + i]     = hasS ? so[i] * g1 : 0.f;
        c[2 * H_ + i] = wo[i] * g2;
    }
}

// ---------------- residual + layernorm ----------------------------------------
__global__ void final_ln_kernel(const float* __restrict__ pre, const float* __restrict__ x,
                                float* __restrict__ out)
{
    const ll row = blockIdx.x;
    const float* p = pre + row * (ll)H_;
    const float* xr = x + row * (ll)H_;
    float* o = out + row * (ll)H_;
    const int tid = threadIdx.x;
    __shared__ float buf[H_];
    __shared__ float red[64];
    __shared__ float stats[2];

    float s = 0.f, ss = 0.f;
    for (int i = tid; i < H_; i += blockDim.x) {
        const float v = 0.5f * (p[i] + xr[i]);
        buf[i] = v;
        s += v;
        ss += v * v;
    }
#pragma unroll
    for (int o2 = 16; o2 > 0; o2 >>= 1) {
        s  += __shfl_xor_sync(0xffffffffu, s, o2);
        ss += __shfl_xor_sync(0xffffffffu, ss, o2);
    }
    if ((tid & 31) == 0) { red[tid >> 5] = s; red[32 + (tid >> 5)] = ss; }
    __syncthreads();
    if (tid == 0) {
        float ts = 0.f, tss = 0.f;
        for (int i = 0; i < (int)(blockDim.x >> 5); i++) { ts += red[i]; tss += red[32 + i]; }
        const float mean = ts / (float)H_;
        const float var = tss / (float)H_ - mean * mean;
        stats[0] = mean;
        stats[1] = rsqrtf(var + 1e-6f);
    }
    __syncthreads();
    const float mean = stats[0], inv = stats[1];
    for (int i = tid; i < H_; i += blockDim.x) o[i] = (buf[i] - mean) * inv;
}

// ------------------------------- launcher --------------------------------------
#define GEMM_SMEM (STG_ * STGF_ * 4)

extern "C" void kernel_launch(void* const* d_in, const int* in_sizes, int n_in,
                              void* d_out, int out_size)
{
    const float* x  = (const float*)d_in[0];
    const float* Wq = (const float*)d_in[1];
    const float* bq = (const float*)d_in[2];
    const float* Wk = (const float*)d_in[3];
    const float* bk = (const float*)d_in[4];
    const float* Wv = (const float*)d_in[5];
    const float* bv = (const float*)d_in[6];
    const float* Wo = (const float*)d_in[7];
    const float* bo = (const float*)d_in[8];
    const float* Wg = (const float*)d_in[9];
    const float* bg = (const float*)d_in[10];
    const float* Wc = (const float*)d_in[11];
    const float* bc = (const float*)d_in[12];
    const float* Ws = (const float*)d_in[13];
    const float* bs = (const float*)d_in[14];
    float* out = (float*)d_out;

    float *Q, *K, *V, *VT, *cmp, *Qc, *Kc, *Vc, *VcT, *S, *comp_out;
    float *Qs, *Ks, *Vs, *VsT, *sel_out, *win_out, *comb, *pre, *gates, *scores;
    float *WqT, *WkT, *WvT, *WcT, *WoT;
    int* idx;
    cudaGetSymbolAddress((void**)&Q, g_Q);
    cudaGetSymbolAddress((void**)&K, g_Kbuf);
    cudaGetSymbolAddress((void**)&V, g_Vbuf);
    cudaGetSymbolAddress((void**)&VT, g_VT);
    cudaGetSymbolAddress((void**)&cmp, g_cmp);
    cudaGetSymbolAddress((void**)&Qc, g_Qc);
    cudaGetSymbolAddress((void**)&Kc, g_Kc);
    cudaGetSymbolAddress((void**)&Vc, g_Vc);
    cudaGetSymbolAddress((void**)&VcT, g_VcT);
    cudaGetSymbolAddress((void**)&S, g_S);
    cudaGetSymbolAddress((void**)&comp_out, g_comp_out);
    cudaGetSymbolAddress((void**)&Qs, g_Qs);
    cudaGetSymbolAddress((void**)&Ks, g_Ks);
    cudaGetSymbolAddress((void**)&Vs, g_Vs);
    cudaGetSymbolAddress((void**)&VsT, g_VsT);
    cudaGetSymbolAddress((void**)&sel_out, g_sel_out);
    cudaGetSymbolAddress((void**)&win_out, g_win_out);
    cudaGetSymbolAddress((void**)&comb, g_comb);
    cudaGetSymbolAddress((void**)&pre, g_pre);
    cudaGetSymbolAddress((void**)&gates, g_gates);
    cudaGetSymbolAddress((void**)&scores, g_scores);
    cudaGetSymbolAddress((void**)&idx, g_idx);
    cudaGetSymbolAddress((void**)&WqT, g_WqT);
    cudaGetSymbolAddress((void**)&WkT, g_WkT);
    cudaGetSymbolAddress((void**)&WvT, g_WvT);
    cudaGetSymbolAddress((void**)&WcT, g_WcT);
    cudaGetSymbolAddress((void**)&WoT, g_WoT);

    cudaFuncSetAttribute(gemm_tt, cudaFuncAttributeMaxDynamicSharedMemorySize, GEMM_SMEM);

    const int MT = B_ * L_;
    const dim3 tb(32, 8);

    gates_scores_kernel<<<MT / 8, 256>>>(x, Wg, bg, Ws, bs, gates, scores);

    // weight transposes (K x N -> N x K)
    transpose_kernel<<<dim3(H_ / 32, H_ / 32, 1), tb>>>(Wq, WqT, H_, H_);
    transpose_kernel<<<dim3(H_ / 32, H_ / 32, 1), tb>>>(Wk, WkT, H_, H_);
    transpose_kernel<<<dim3(H_ / 32, H_ / 32, 1), tb>>>(Wv, WvT, H_, H_);
    transpose_kernel<<<dim3(H_ / 32, (4 * H_) / 32, 1), tb>>>(Wc, WcT, 4 * H_, H_);
    transpose_kernel<<<dim3(H_ / 32, (3 * H_) / 32, 1), tb>>>(Wo, WoT, 3 * H_, H_);

    // full-sequence QKV
    {
        dim3 g(H_ / 128, MT / 128, 1);
        gemm_tt<<<g, 128, GEMM_SMEM>>>(x, WqT, bq, Q, MT, H_, H_, 1.f, H_, H_, 0, 0, 1, 0, 0, 0);
        gemm_tt<<<g, 128, GEMM_SMEM>>>(x, WkT, bk, K, MT, H_, H_, 1.f, H_, H_, 0, 0, 1, 0, 0, 0);
        gemm_tt<<<g, 128, GEMM_SMEM>>>(x, WvT, bv, V, MT, H_, H_, 1.f, H_, H_, 0, 0, 1, 0, 0, 0);
    }
    transpose_kernel<<<dim3(H_ / 32, L_ / 32, B_), tb>>>(V, VT, L_, H_);

    // compressed branch projections
    {
        dim3 g(H_ / 128, (B_ * LC_) / 128, 1);
        gemm_tt<<<g, 128, GEMM_SMEM>>>(x, WcT, bc, cmp, B_ * LC_, H_, 4 * H_, 1.f, 4 * H_, 4 * H_, 0, 0, 1, 0, 0, 0);
        gemm_tt<<<g, 128, GEMM_SMEM>>>(cmp, WqT, bq, Qc, B_ * LC_, H_, H_, 1.f, H_, H_, 0, 0, 1, 0, 0, 0);
        gemm_tt<<<g, 128, GEMM_SMEM>>>(cmp, WkT, bk, Kc, B_ * LC_, H_, H_, 1.f, H_, H_, 0, 0, 1, 0, 0, 0);
        gemm_tt<<<g, 128, GEMM_SMEM>>>(cmp, WvT, bv, Vc, B_ * LC_, H_, H_, 1.f, H_, H_, 0, 0, 1, 0, 0, 0);
    }
    transpose_kernel<<<dim3(H_ / 32, LC_ / 32, B_), tb>>>(Vc, VcT, LC_, H_);

    topk_kernel<<<B_, 512>>>(scores, idx);
    gather_kernel<<<dim3(KSEL_, B_), 256>>>(Q, K, V, idx, Qs, Ks, Vs);
    transpose_kernel<<<dim3(H_ / 32, KSEL_ / 32, B_), tb>>>(Vs, VsT, KSEL_, H_);

    // compressed attention
    gemm_tt<<<dim3(LC_ / 128, LC_ / 128, B_), 128, GEMM_SMEM>>>(
        Qc, Kc, nullptr, S, LC_, LC_, H_, SCALE_, H_, H_,
        (ll)LC_ * H_, 0, 1, (ll)LC_ * H_, 0, (ll)LC_ * LC_);
    softmax_kernel<<<B_ * LC_, 256>>>(S, LC_);
    gemm_tt<<<dim3(H_ / 128, LC_ / 128, B_), 128, GEMM_SMEM>>>(
        S, VcT, nullptr, comp_out, LC_, H_, LC_, 1.f, LC_, LC_,
        (ll)LC_ * LC_, 0, 1, (ll)H_ * LC_, 0, (ll)LC_ * H_);

    // selected attention
    gemm_tt<<<dim3(KSEL_ / 128, KSEL_ / 128, B_), 128, GEMM_SMEM>>>(
        Qs, Ks, nullptr, S, KSEL_, KSEL_, H_, SCALE_, H_, H_,
        (ll)KSEL_ * H_, 0, 1, (ll)KSEL_ * H_, 0, (ll)KSEL_ * KSEL_);
    softmax_kernel<<<B_ * KSEL_, 256>>>(S, KSEL_);
    gemm_tt<<<dim3(H_ / 128, KSEL_ / 128, B_), 128, GEMM_SMEM>>>(
        S, VsT, nullptr, sel_out, KSEL_, H_, KSEL_, 1.f, KSEL_, KSEL_,
        (ll)KSEL_ * KSEL_, 0, 1, (ll)H_ * KSEL_, 0, (ll)KSEL_ * H_);

    // window attention (windows = contiguous QKV rows starting at 128*w)
    gemm_tt<<<dim3(WIN_ / 128, WIN_ / 128, B_ * NW_), 128, GEMM_SMEM>>>(
        Q, K, nullptr, S, WIN_, WIN_, H_, SCALE_, H_, H_,
        (ll)L_ * H_, (ll)128 * H_, NW_,
        (ll)L_ * H_, (ll)128 * H_, (ll)WIN_ * WIN_);
    softmax_kernel<<<B_ * NW_ * WIN_, 256>>>(S, WIN_);
    gemm_tt<<<dim3(H_ / 128, WIN_ / 128, B_ * NW_), 128, GEMM_SMEM>>>(
        S, VT, nullptr, win_out, WIN_, H_, WIN_, 1.f, WIN_, L_,
        (ll)NW_ * WIN_ * WIN_, (ll)WIN_ * WIN_, NW_,
        (ll)H_ * L_, 128, (ll)WIN_ * H_);

    assemble_kernel<<<MT, 256>>>(comp_out, sel_out, win_out, gates, comb);
    gemm_tt<<<dim3(H_ / 128, MT / 128, 1), 128, GEMM_SMEM>>>(
        comb, WoT, bo, pre, MT, H_, 3 * H_, 1.f, 3 * H_, 3 * H_, 0, 0, 1, 0, 0, 0);
    final_ln_kernel<<<MT, 256>>>(pre, x, out);
}

// round 4
// speedup vs baseline: 1.3968x; 1.3968x over previous
#include <cuda_runtime.h>
#include <math.h>
#include <stdint.h>

#define B_    4
#define L_    4096
#define H_    1024
#define LC_   1024
#define KSEL_ 512
#define WIN_  256
#define NW_   16
#define SCALE_ 0.125f

typedef long long ll;

// ---------------- scratch -----------------------------------------------------
__device__ float g_Q[(size_t)B_ * L_ * H_];
__device__ float g_Kbuf[(size_t)B_ * L_ * H_];
__device__ float g_Vbuf[(size_t)B_ * L_ * H_];
__device__ float g_VT[(size_t)B_ * H_ * L_];
__device__ float g_cmp[(size_t)B_ * LC_ * H_];
__device__ float g_Qc[(size_t)B_ * LC_ * H_];
__device__ float g_Kc[(size_t)B_ * LC_ * H_];
__device__ float g_Vc[(size_t)B_ * LC_ * H_];
__device__ float g_VcT[(size_t)B_ * H_ * LC_];
__device__ float g_S[(size_t)B_ * LC_ * LC_];
__device__ float g_comp_out[(size_t)B_ * LC_ * H_];
__device__ float g_Qs[(size_t)B_ * KSEL_ * H_];
__device__ float g_Ks[(size_t)B_ * KSEL_ * H_];
__device__ float g_Vs[(size_t)B_ * KSEL_ * H_];
__device__ float g_VsT[(size_t)B_ * H_ * KSEL_];
__device__ float g_sel_out[(size_t)B_ * KSEL_ * H_];
__device__ float g_win_out[(size_t)B_ * L_ * H_];
__device__ float g_comb[(size_t)B_ * L_ * 3 * H_];
__device__ float g_pre[(size_t)B_ * L_ * H_];
__device__ float g_gates[(size_t)B_ * L_ * 3];
__device__ float g_scores[(size_t)B_ * L_];
__device__ int   g_idx[B_ * KSEL_];
__device__ float g_WqT[(size_t)H_ * H_];
__device__ float g_WkT[(size_t)H_ * H_];
__device__ float g_WvT[(size_t)H_ * H_];
__device__ float g_WcT[(size_t)4 * H_ * H_];
__device__ float g_WoT[(size_t)3 * H_ * H_];

// ---------------- asm helpers --------------------------------------------------
__device__ __forceinline__ void mma_tf32(float& c0, float& c1, float& c2, float& c3,
                                         uint32_t a0, uint32_t a1, uint32_t a2, uint32_t a3,
                                         uint32_t b0, uint32_t b1) {
    asm volatile(
        "mma.sync.aligned.m16n8k8.row.col.f32.tf32.tf32.f32 "
        "{%0,%1,%2,%3}, {%4,%5,%6,%7}, {%8,%9}, {%0,%1,%2,%3};"
        : "+f"(c0), "+f"(c1), "+f"(c2), "+f"(c3)
        : "r"(a0), "r"(a1), "r"(a2), "r"(a3), "r"(b0), "r"(b1));
}
__device__ __forceinline__ void ldsm4(uint32_t& r0, uint32_t& r1, uint32_t& r2, uint32_t& r3,
                                      uint32_t addr) {
    asm volatile("ldmatrix.sync.aligned.m8n8.x4.shared.b16 {%0,%1,%2,%3}, [%4];"
                 : "=r"(r0), "=r"(r1), "=r"(r2), "=r"(r3) : "r"(addr));
}
__device__ __forceinline__ void cpasync16(uint32_t dst, const float* src) {
    asm volatile("cp.async.cg.shared.global [%0], [%1], 16;" :: "r"(dst), "l"(src));
}
__device__ __forceinline__ void cp_commit() { asm volatile("cp.async.commit_group;"); }
template <int N> __device__ __forceinline__ void cp_wait() {
    asm volatile("cp.async.wait_group %0;" :: "n"(N));
}

// ---------------- tf32 TC GEMM: C = alpha*A*B^T + bias -------------------------
// A: MxK row-major ld=lda. B: NxK row-major ld=ldb. C: MxN row-major.
// fp32 inputs consumed as tf32 (truncation). 256 threads, 8 warps 4x2,
// warp tile 32x64, 4-stage cp.async pipeline.
// REQUIRES M%128==0, N%128==0, K%16==0, K>=64.
#define BK_     16
#define ASTR_   20
#define STG_    4
#define STGF_   (2 * 128 * ASTR_)            // floats per stage (A+B)
#define GEMM_SMEM (STG_ * STGF_ * 4)         // 81920 bytes

__global__ void __launch_bounds__(256, 2)
gemm_tt(const float* __restrict__ A, const float* __restrict__ Bm,
        const float* __restrict__ bias, float* __restrict__ C,
        int M, int N, int K, float alpha, int lda, int ldb,
        ll saO, ll saI, int innerCnt, ll sbO, ll sbI, ll sC)
{
    extern __shared__ float sm[];
    const int z = blockIdx.z;
    const float* Ab = A + (ll)(z / innerCnt) * saO + (ll)(z % innerCnt) * saI
                        + (ll)blockIdx.y * 128 * lda;
    const float* Bb = Bm + (ll)(z / innerCnt) * sbO + (ll)(z % innerCnt) * sbI
                        + (ll)blockIdx.x * 128 * ldb;
    float* Cb = C + (ll)z * sC;

    const int tid = threadIdx.x, lane = tid & 31, warp = tid >> 5;
    const int wm = (warp & 3) * 32, wn = (warp >> 2) * 64;
    const uint32_t smemBase = (uint32_t)__cvta_generic_to_shared(sm);

    // cp.async mapping: thread -> row tid>>1, float col (tid&1)*8 (two 16B chunks)
    const int ldRow = tid >> 1;
    const int ldCol = (tid & 1) << 3;
    const float* aSrc = Ab + (ll)ldRow * lda + ldCol;
    const float* bSrc = Bb + (ll)ldRow * ldb + ldCol;
    const uint32_t dstA = smemBase + (uint32_t)(ldRow * ASTR_ + ldCol) * 4u;
    const uint32_t dstB = dstA + 2560u * 4u;

    // ldmatrix fragment addresses
    const int laneRow = lane & 15;
    const int laneHalf = (lane >> 4) << 2;
    int aOff[2], bOff[4];
#pragma unroll
    for (int mt = 0; mt < 2; mt++) aOff[mt] = (wm + mt * 16 + laneRow) * ASTR_ + laneHalf;
#pragma unroll
    for (int np = 0; np < 4; np++) bOff[np] = 2560 + (wn + np * 16 + laneRow) * ASTR_ + laneHalf;

    float acc[2][8][4];
#pragma unroll
    for (int mt = 0; mt < 2; mt++)
#pragma unroll
        for (int nt = 0; nt < 8; nt++)
#pragma unroll
            for (int i = 0; i < 4; i++) acc[mt][nt][i] = 0.f;

    const int kTiles = K >> 4;

    // prologue: stages 0..STG_-2
#pragma unroll
    for (int s = 0; s < STG_ - 1; s++) {
        const uint32_t da = dstA + (uint32_t)(s * STGF_) * 4u;
        const uint32_t db = dstB + (uint32_t)(s * STGF_) * 4u;
        cpasync16(da,      aSrc + s * BK_);
        cpasync16(da + 16, aSrc + s * BK_ + 4);
        cpasync16(db,      bSrc + s * BK_);
        cpasync16(db + 16, bSrc + s * BK_ + 4);
        cp_commit();
    }

    for (int kt = 0; kt < kTiles; kt++) {
        cp_wait<STG_ - 2>();
        __syncthreads();

        if (kt + STG_ - 1 < kTiles) {
            const int s = kt + STG_ - 1;
            const int slot = s & (STG_ - 1);
            const uint32_t da = dstA + (uint32_t)(slot * STGF_) * 4u;
            const uint32_t db = dstB + (uint32_t)(slot * STGF_) * 4u;
            cpasync16(da,      aSrc + s * BK_);
            cpasync16(da + 16, aSrc + s * BK_ + 4);
            cpasync16(db,      bSrc + s * BK_);
            cpasync16(db + 16, bSrc + s * BK_ + 4);
        }
        cp_commit();

        const uint32_t slotB = smemBase + (uint32_t)((kt & (STG_ - 1)) * STGF_) * 4u;
#pragma unroll
        for (int ks = 0; ks < 16; ks += 8) {
            uint32_t afr[2][4], bfr[4][4];
#pragma unroll
            for (int mt = 0; mt < 2; mt++)
                ldsm4(afr[mt][0], afr[mt][1], afr[mt][2], afr[mt][3],
                      slotB + (uint32_t)(aOff[mt] + ks) * 4u);
#pragma unroll
            for (int np = 0; np < 4; np++)
                ldsm4(bfr[np][0], bfr[np][1], bfr[np][2], bfr[np][3],
                      slotB + (uint32_t)(bOff[np] + ks) * 4u);
#pragma unroll
            for (int mt = 0; mt < 2; mt++)
#pragma unroll
                for (int np = 0; np < 4; np++) {
                    mma_tf32(acc[mt][2 * np][0], acc[mt][2 * np][1],
                             acc[mt][2 * np][2], acc[mt][2 * np][3],
                             afr[mt][0], afr[mt][1], afr[mt][2], afr[mt][3],
                             bfr[np][0], bfr[np][2]);
                    mma_tf32(acc[mt][2 * np + 1][0], acc[mt][2 * np + 1][1],
                             acc[mt][2 * np + 1][2], acc[mt][2 * np + 1][3],
                             afr[mt][0], afr[mt][1], afr[mt][2], afr[mt][3],
                             bfr[np][1], bfr[np][3]);
                }
        }
    }

    __syncthreads();   // protect smem before exit epilogue reuse is not needed; cheap
    const int g = lane >> 2, tg = lane & 3;
#pragma unroll
    for (int mt = 0; mt < 2; mt++) {
        const int r0 = blockIdx.y * 128 + wm + mt * 16 + g;
#pragma unroll
        for (int nt = 0; nt < 8; nt++) {
            const int col = blockIdx.x * 128 + wn + nt * 8 + tg * 2;
            float2 bv = make_float2(0.f, 0.f);
            if (bias) bv = *(const float2*)&bias[col];
            float2 o;
            o.x = alpha * acc[mt][nt][0] + bv.x;
            o.y = alpha * acc[mt][nt][1] + bv.y;
            *(float2*)(Cb + (ll)r0 * N + col) = o;
            o.x = alpha * acc[mt][nt][2] + bv.x;
            o.y = alpha * acc[mt][nt][3] + bv.y;
            *(float2*)(Cb + (ll)(r0 + 8) * N + col) = o;
        }
    }
}

// ---------------- batched transpose -------------------------------------------
__global__ void transpose_kernel(const float* __restrict__ in, float* __restrict__ out,
                                 int R, int C)
{
    __shared__ float t[32][33];
    const int z = blockIdx.z;
    const float* ib = in + (ll)z * R * C;
    float* ob = out + (ll)z * R * C;
    const int c0 = blockIdx.x * 32, r0 = blockIdx.y * 32;
#pragma unroll
    for (int i = threadIdx.y; i < 32; i += 8)
        t[i][threadIdx.x] = ib[(ll)(r0 + i) * C + c0 + threadIdx.x];
    __syncthreads();
#pragma unroll
    for (int i = threadIdx.y; i < 32; i += 8)
        ob[(ll)(c0 + i) * R + r0 + threadIdx.x] = t[threadIdx.x][i];
}

// ---------------- gates + selection scores ------------------------------------
__global__ void gates_scores_kernel(const float* __restrict__ x,
                                    const float* __restrict__ Wg, const float* __restrict__ bg,
                                    const float* __restrict__ Ws, const float* __restrict__ bs,
                                    float* __restrict__ gates, float* __restrict__ scores)
{
    const int row = blockIdx.x * (blockDim.x >> 5) + (threadIdx.x >> 5);
    const int lane = threadIdx.x & 31;
    if (row >= B_ * L_) return;
    const float* xr = x + (ll)row * H_;
    float a0 = 0.f, a1 = 0.f, a2 = 0.f, a3 = 0.f;
    for (int k = lane; k < H_; k += 32) {
        const float xv = xr[k];
        a0 += xv * Wg[k * 3 + 0];
        a1 += xv * Wg[k * 3 + 1];
        a2 += xv * Wg[k * 3 + 2];
        a3 += xv * Ws[k];
    }
#pragma unroll
    for (int o = 16; o > 0; o >>= 1) {
        a0 += __shfl_down_sync(0xffffffffu, a0, o);
        a1 += __shfl_down_sync(0xffffffffu, a1, o);
        a2 += __shfl_down_sync(0xffffffffu, a2, o);
        a3 += __shfl_down_sync(0xffffffffu, a3, o);
    }
    if (lane == 0) {
        float s0 = 1.f / (1.f + expf(-(a0 + bg[0])));
        float s1 = 1.f / (1.f + expf(-(a1 + bg[1])));
        float s2 = 1.f / (1.f + expf(-(a2 + bg[2])));
        float inv = 1.f / (s0 + s1 + s2 + 1e-6f);
        gates[row * 3 + 0] = s0 * inv;
        gates[row * 3 + 1] = s1 * inv;
        gates[row * 3 + 2] = s2 * inv;
        scores[row] = a3 + bs[0];
    }
}

// ---------------- top-512 per batch ------------------------------------------
__global__ void topk_kernel(const float* __restrict__ scores, int* __restrict__ idx_out)
{
    __shared__ float sv[L_];
    __shared__ int   si[L_];
    __shared__ int   top[KSEL_];
    const int b = blockIdx.x;
    const float* s = scores + (ll)b * L_;
    for (int i = threadIdx.x; i < L_; i += blockDim.x) { sv[i] = s[i]; si[i] = i; }
    __syncthreads();
    for (int k = 2; k <= L_; k <<= 1)
        for (int j = k >> 1; j > 0; j >>= 1) {
            for (int i = threadIdx.x; i < L_; i += blockDim.x) {
                const int ixj = i ^ j;
                if (ixj > i) {
                    const bool desc = ((i & k) == 0);
                    const float a = sv[i], c = sv[ixj];
                    const bool sw = desc ? (a < c) : (a > c);
                    if (sw) {
                        sv[i] = c; sv[ixj] = a;
                        const int t = si[i]; si[i] = si[ixj]; si[ixj] = t;
                    }
                }
            }
            __syncthreads();
        }
    for (int i = threadIdx.x; i < KSEL_; i += blockDim.x) top[i] = si[i];
    __syncthreads();
    for (int k = 2; k <= KSEL_; k <<= 1)
        for (int j = k >> 1; j > 0; j >>= 1) {
            for (int i = threadIdx.x; i < KSEL_; i += blockDim.x) {
                const int ixj = i ^ j;
                if (ixj > i) {
                    const bool asc = ((i & k) == 0);
                    const int a = top[i], c = top[ixj];
                    const bool sw = asc ? (a > c) : (a < c);
                    if (sw) { top[i] = c; top[ixj] = a; }
                }
            }
            __syncthreads();
        }
    for (int i = threadIdx.x; i < KSEL_; i += blockDim.x) idx_out[b * KSEL_ + i] = top[i];
}

// ---------------- gather selected rows ----------------------------------------
__global__ void gather_kernel(const float* __restrict__ Q, const float* __restrict__ K,
                              const float* __restrict__ V, const int* __restrict__ idx,
                              float* __restrict__ Qs, float* __restrict__ Ks, float* __restrict__ Vs)
{
    const int b = blockIdx.y, r = blockIdx.x;
    const int src = idx[b * KSEL_ + r];
    const ll so = ((ll)b * L_ + src) * H_;
    const ll dst = ((ll)b * KSEL_ + r) * H_;
    for (int i = threadIdx.x; i < H_; i += blockDim.x) {
        Qs[dst + i] = Q[so + i];
        Ks[dst + i] = K[so + i];
        Vs[dst + i] = V[so + i];
    }
}

// ---------------- row softmax --------------------------------------------------
__global__ void softmax_kernel(float* __restrict__ S, int n)
{
    const ll row = blockIdx.x;
    float* s = S + row * (ll)n;
    const int tid = threadIdx.x;
    __shared__ float red[32];
    __shared__ float bc;

    float m = -1e30f;
    for (int i = tid; i < n; i += blockDim.x) m = fmaxf(m, s[i]);
#pragma unroll
    for (int o = 16; o > 0; o >>= 1) m = fmaxf(m, __shfl_xor_sync(0xffffffffu, m, o));
    if ((tid & 31) == 0) red[tid >> 5] = m;
    __syncthreads();
    if (tid == 0) {
        float mm = -1e30f;
        for (int i = 0; i < (int)(blockDim.x >> 5); i++) mm = fmaxf(mm, red[i]);
        bc = mm;
    }
    __syncthreads();
    m = bc;
    __syncthreads();

    float sum = 0.f;
    for (int i = tid; i < n; i += blockDim.x) {
        const float e = expf(s[i] - m);
        s[i] = e;
        sum += e;
    }
#pragma unroll
    for (int o = 16; o > 0; o >>= 1) sum += __shfl_xor_sync(0xffffffffu, sum, o);
    if ((tid & 31) == 0) red[tid >> 5] = sum;
    __syncthreads();
    if (tid == 0) {
        float ss = 0.f;
        for (int i = 0; i < (int)(blockDim.x >> 5); i++) ss += red[i];
        bc = 1.f / ss;
    }
    __syncthreads();
    const float inv = bc;
    for (int i = tid; i < n; i += blockDim.x) s[i] *= inv;
}

// ---------------- assemble gated combined -------------------------------------
__global__ void assemble_kernel(const float* __restrict__ comp_out, const float* __restrict__ sel_out,
                                const float* __restrict__ win_out, const float* __restrict__ gates,
                                float* __restrict__ comb)
{
    const ll t = blockIdx.x;
    const int b = (int)(t >> 12), l = (int)(t & 4095);
    const float g0 = gates[t * 3 + 0], g1 = gates[t * 3 + 1], g2 = gates[t * 3 + 2];
    float* c = comb + t * (ll)(3 * H_);
    const float* co = comp_out + ((ll)b * LC_ + l) * H_;
    const float* so = sel_out + ((ll)b * KSEL_ + l) * H_;
    const float* wo = win_out + t * (ll)H_;
    const bool hasC = (l < LC_), hasS = (l < KSEL_);
    for (int i = threadIdx.x; i < H_; i += blockDim.x) {
        c[i]          = hasC ? co[i] * g0 : 0.f;
        c[H_ + i]     = hasS ? so[i] * g1 : 0.f;
        c[2 * H_ + i] = wo[i] * g2;
    }
}

// ---------------- residual + layernorm ----------------------------------------
__global__ void final_ln_kernel(const float* __restrict__ pre, const float* __restrict__ x,
                                float* __restrict__ out)
{
    const ll row = blockIdx.x;
    const float* p = pre + row * (ll)H_;
    const float* xr = x + row * (ll)H_;
    float* o = out + row * (ll)H_;
    const int tid = threadIdx.x;
    __shared__ float buf[H_];
    __shared__ float red[64];
    __shared__ float stats[2];

    float s = 0.f, ss = 0.f;
    for (int i = tid; i < H_; i += blockDim.x) {
        const float v = 0.5f * (p[i] + xr[i]);
        buf[i] = v;
        s += v;
        ss += v * v;
    }
#pragma unroll
    for (int o2 = 16; o2 > 0; o2 >>= 1) {
        s  += __shfl_xor_sync(0xffffffffu, s, o2);
        ss += __shfl_xor_sync(0xffffffffu, ss, o2);
    }
    if ((tid & 31) == 0) { red[tid >> 5] = s; red[32 + (tid >> 5)] = ss; }
    __syncthreads();
    if (tid == 0) {
        float ts = 0.f, tss = 0.f;
        for (int i = 0; i < (int)(blockDim.x >> 5); i++) { ts += red[i]; tss += red[32 + i]; }
        const float mean = ts / (float)H_;
        const float var = tss / (float)H_ - mean * mean;
        stats[0] = mean;
        stats[1] = rsqrtf(var + 1e-6f);
    }
    __syncthreads();
    const float mean = stats[0], inv = stats[1];
    for (int i = tid; i < H_; i += blockDim.x) o[i] = (buf[i] - mean) * inv;
}

// ------------------------------- launcher --------------------------------------
extern "C" void kernel_launch(void* const* d_in, const int* in_sizes, int n_in,
                              void* d_out, int out_size)
{
    const float* x  = (const float*)d_in[0];
    const float* Wq = (const float*)d_in[1];
    const float* bq = (const float*)d_in[2];
    const float* Wk = (const float*)d_in[3];
    const float* bk = (const float*)d_in[4];
    const float* Wv = (const float*)d_in[5];
    const float* bv = (const float*)d_in[6];
    const float* Wo = (const float*)d_in[7];
    const float* bo = (const float*)d_in[8];
    const float* Wg = (const float*)d_in[9];
    const float* bg = (const float*)d_in[10];
    const float* Wc = (const float*)d_in[11];
    const float* bc = (const float*)d_in[12];
    const float* Ws = (const float*)d_in[13];
    const float* bs = (const float*)d_in[14];
    float* out = (float*)d_out;

    float *Q, *K, *V, *VT, *cmp, *Qc, *Kc, *Vc, *VcT, *S, *comp_out;
    float *Qs, *Ks, *Vs, *VsT, *sel_out, *win_out, *comb, *pre, *gates, *scores;
    float *WqT, *WkT, *WvT, *WcT, *WoT;
    int* idx;
    cudaGetSymbolAddress((void**)&Q, g_Q);
    cudaGetSymbolAddress((void**)&K, g_Kbuf);
    cudaGetSymbolAddress((void**)&V, g_Vbuf);
    cudaGetSymbolAddress((void**)&VT, g_VT);
    cudaGetSymbolAddress((void**)&cmp, g_cmp);
    cudaGetSymbolAddress((void**)&Qc, g_Qc);
    cudaGetSymbolAddress((void**)&Kc, g_Kc);
    cudaGetSymbolAddress((void**)&Vc, g_Vc);
    cudaGetSymbolAddress((void**)&VcT, g_VcT);
    cudaGetSymbolAddress((void**)&S, g_S);
    cudaGetSymbolAddress((void**)&comp_out, g_comp_out);
    cudaGetSymbolAddress((void**)&Qs, g_Qs);
    cudaGetSymbolAddress((void**)&Ks, g_Ks);
    cudaGetSymbolAddress((void**)&Vs, g_Vs);
    cudaGetSymbolAddress((void**)&VsT, g_VsT);
    cudaGetSymbolAddress((void**)&sel_out, g_sel_out);
    cudaGetSymbolAddress((void**)&win_out, g_win_out);
    cudaGetSymbolAddress((void**)&comb, g_comb);
    cudaGetSymbolAddress((void**)&pre, g_pre);
    cudaGetSymbolAddress((void**)&gates, g_gates);
    cudaGetSymbolAddress((void**)&scores, g_scores);
    cudaGetSymbolAddress((void**)&idx, g_idx);
    cudaGetSymbolAddress((void**)&WqT, g_WqT);
    cudaGetSymbolAddress((void**)&WkT, g_WkT);
    cudaGetSymbolAddress((void**)&WvT, g_WvT);
    cudaGetSymbolAddress((void**)&WcT, g_WcT);
    cudaGetSymbolAddress((void**)&WoT, g_WoT);

    cudaFuncSetAttribute(gemm_tt, cudaFuncAttributeMaxDynamicSharedMemorySize, GEMM_SMEM);

    const int MT = B_ * L_;
    const dim3 tb(32, 8);

    gates_scores_kernel<<<MT / 8, 256>>>(x, Wg, bg, Ws, bs, gates, scores);

    transpose_kernel<<<dim3(H_ / 32, H_ / 32, 1), tb>>>(Wq, WqT, H_, H_);
    transpose_kernel<<<dim3(H_ / 32, H_ / 32, 1), tb>>>(Wk, WkT, H_, H_);
    transpose_kernel<<<dim3(H_ / 32, H_ / 32, 1), tb>>>(Wv, WvT, H_, H_);
    transpose_kernel<<<dim3(H_ / 32, (4 * H_) / 32, 1), tb>>>(Wc, WcT, 4 * H_, H_);
    transpose_kernel<<<dim3(H_ / 32, (3 * H_) / 32, 1), tb>>>(Wo, WoT, 3 * H_, H_);

    {
        dim3 g(H_ / 128, MT / 128, 1);
        gemm_tt<<<g, 256, GEMM_SMEM>>>(x, WqT, bq, Q, MT, H_, H_, 1.f, H_, H_, 0, 0, 1, 0, 0, 0);
        gemm_tt<<<g, 256, GEMM_SMEM>>>(x, WkT, bk, K, MT, H_, H_, 1.f, H_, H_, 0, 0, 1, 0, 0, 0);
        gemm_tt<<<g, 256, GEMM_SMEM>>>(x, WvT, bv, V, MT, H_, H_, 1.f, H_, H_, 0, 0, 1, 0, 0, 0);
    }
    transpose_kernel<<<dim3(H_ / 32, L_ / 32, B_), tb>>>(V, VT, L_, H_);

    {
        dim3 g(H_ / 128, (B_ * LC_) / 128, 1);
        gemm_tt<<<g, 256, GEMM_SMEM>>>(x, WcT, bc, cmp, B_ * LC_, H_, 4 * H_, 1.f, 4 * H_, 4 * H_, 0, 0, 1, 0, 0, 0);
        gemm_tt<<<g, 256, GEMM_SMEM>>>(cmp, WqT, bq, Qc, B_ * LC_, H_, H_, 1.f, H_, H_, 0, 0, 1, 0, 0, 0);
        gemm_tt<<<g, 256, GEMM_SMEM>>>(cmp, WkT, bk, Kc, B_ * LC_, H_, H_, 1.f, H_, H_, 0, 0, 1, 0, 0, 0);
        gemm_tt<<<g, 256, GEMM_SMEM>>>(cmp, WvT, bv, Vc, B_ * LC_, H_, H_, 1.f, H_, H_, 0, 0, 1, 0, 0, 0);
    }
    transpose_kernel<<<dim3(H_ / 32, LC_ / 32, B_), tb>>>(Vc, VcT, LC_, H_);

    topk_kernel<<<B_, 512>>>(scores, idx);
    gather_kernel<<<dim3(KSEL_, B_), 256>>>(Q, K, V, idx, Qs, Ks, Vs);
    transpose_kernel<<<dim3(H_ / 32, KSEL_ / 32, B_), tb>>>(Vs, VsT, KSEL_, H_);

    // compressed attention
    gemm_tt<<<dim3(LC_ / 128, LC_ / 128, B_), 256, GEMM_SMEM>>>(
        Qc, Kc, nullptr, S, LC_, LC_, H_, SCALE_, H_, H_,
        (ll)LC_ * H_, 0, 1, (ll)LC_ * H_, 0, (ll)LC_ * LC_);
    softmax_kernel<<<B_ * LC_, 256>>>(S, LC_);
    gemm_tt<<<dim3(H_ / 128, LC_ / 128, B_), 256, GEMM_SMEM>>>(
        S, VcT, nullptr, comp_out, LC_, H_, LC_, 1.f, LC_, LC_,
        (ll)LC_ * LC_, 0, 1, (ll)H_ * LC_, 0, (ll)LC_ * H_);

    // selected attention
    gemm_tt<<<dim3(KSEL_ / 128, KSEL_ / 128, B_), 256, GEMM_SMEM>>>(
        Qs, Ks, nullptr, S, KSEL_, KSEL_, H_, SCALE_, H_, H_,
        (ll)KSEL_ * H_, 0, 1, (ll)KSEL_ * H_, 0, (ll)KSEL_ * KSEL_);
    softmax_kernel<<<B_ * KSEL_, 256>>>(S, KSEL_);
    gemm_tt<<<dim3(H_ / 128, KSEL_ / 128, B_), 256, GEMM_SMEM>>>(
        S, VsT, nullptr, sel_out, KSEL_, H_, KSEL_, 1.f, KSEL_, KSEL_,
        (ll)KSEL_ * KSEL_, 0, 1, (ll)H_ * KSEL_, 0, (ll)KSEL_ * H_);

    // window attention
    gemm_tt<<<dim3(WIN_ / 128, WIN_ / 128, B_ * NW_), 256, GEMM_SMEM>>>(
        Q, K, nullptr, S, WIN_, WIN_, H_, SCALE_, H_, H_,
        (ll)L_ * H_, (ll)128 * H_, NW_,
        (ll)L_ * H_, (ll)128 * H_, (ll)WIN_ * WIN_);
    softmax_kernel<<<B_ * NW_ * WIN_, 256>>>(S, WIN_);
    gemm_tt<<<dim3(H_ / 128, WIN_ / 128, B_ * NW_), 256, GEMM_SMEM>>>(
        S, VT, nullptr, win_out, WIN_, H_, WIN_, 1.f, WIN_, L_,
        (ll)NW_ * WIN_ * WIN_, (ll)WIN_ * WIN_, NW_,
        (ll)H_ * L_, 128, (ll)WIN_ * H_);

    assemble_kernel<<<MT, 256>>>(comp_out, sel_out, win_out, gates, comb);
    gemm_tt<<<dim3(H_ / 128, MT / 128, 1), 256, GEMM_SMEM>>>(
        comb, WoT, bo, pre, MT, H_, 3 * H_, 1.f, 3 * H_, 3 * H_, 0, 0, 1, 0, 0, 0);
    final_ln_kernel<<<MT, 256>>>(pre, x, out);
}

// round 5
// speedup vs baseline: 2.6734x; 1.9140x over previous
#include <cuda_runtime.h>
#include <cuda_bf16.h>
#include <math.h>
#include <stdint.h>

#define B_    4
#define L_    4096
#define H_    1024
#define LC_   1024
#define KSEL_ 512
#define WIN_  256
#define NW_   16
#define SCALE_ 0.125f

typedef long long ll;
typedef __nv_bfloat16 bf16;

// ---------------- scratch -----------------------------------------------------
__device__ bf16  g_xh[(size_t)B_ * L_ * H_];
__device__ bf16  g_Q[(size_t)B_ * L_ * H_];
__device__ bf16  g_Kb[(size_t)B_ * L_ * H_];
__device__ bf16  g_Vb[(size_t)B_ * L_ * H_];
__device__ bf16  g_VT[(size_t)B_ * H_ * L_];
__device__ bf16  g_cmp[(size_t)B_ * LC_ * H_];
__device__ bf16  g_Qc[(size_t)B_ * LC_ * H_];
__device__ bf16  g_Kc[(size_t)B_ * LC_ * H_];
__device__ bf16  g_Vc[(size_t)B_ * LC_ * H_];
__device__ bf16  g_VcT[(size_t)B_ * H_ * LC_];
__device__ float g_S[(size_t)B_ * LC_ * LC_];
__device__ bf16  g_P[(size_t)B_ * LC_ * LC_];
__device__ float g_comp_out[(size_t)B_ * LC_ * H_];
__device__ bf16  g_Qs[(size_t)B_ * KSEL_ * H_];
__device__ bf16  g_Ks[(size_t)B_ * KSEL_ * H_];
__device__ bf16  g_Vs[(size_t)B_ * KSEL_ * H_];
__device__ bf16  g_VsT[(size_t)B_ * H_ * KSEL_];
__device__ float g_sel_out[(size_t)B_ * KSEL_ * H_];
__device__ float g_win_out[(size_t)B_ * L_ * H_];
__device__ bf16  g_comb[(size_t)B_ * L_ * 3 * H_];
__device__ float g_pre[(size_t)B_ * L_ * H_];
__device__ float g_gates[(size_t)B_ * L_ * 3];
__device__ float g_scores[(size_t)B_ * L_];
__device__ int   g_idx[B_ * KSEL_];
__device__ bf16  g_WqT[(size_t)H_ * H_];
__device__ bf16  g_WkT[(size_t)H_ * H_];
__device__ bf16  g_WvT[(size_t)H_ * H_];
__device__ bf16  g_WcT[(size_t)4 * H_ * H_];
__device__ bf16  g_WoT[(size_t)3 * H_ * H_];

// ---------------- asm helpers --------------------------------------------------
__device__ __forceinline__ void mma_bf16(float& c0, float& c1, float& c2, float& c3,
                                         uint32_t a0, uint32_t a1, uint32_t a2, uint32_t a3,
                                         uint32_t b0, uint32_t b1) {
    asm volatile(
        "mma.sync.aligned.m16n8k16.row.col.f32.bf16.bf16.f32 "
        "{%0,%1,%2,%3}, {%4,%5,%6,%7}, {%8,%9}, {%0,%1,%2,%3};"
        : "+f"(c0), "+f"(c1), "+f"(c2), "+f"(c3)
        : "r"(a0), "r"(a1), "r"(a2), "r"(a3), "r"(b0), "r"(b1));
}
__device__ __forceinline__ void ldsm4(uint32_t& r0, uint32_t& r1, uint32_t& r2, uint32_t& r3,
                                      uint32_t addr) {
    asm volatile("ldmatrix.sync.aligned.m8n8.x4.shared.b16 {%0,%1,%2,%3}, [%4];"
                 : "=r"(r0), "=r"(r1), "=r"(r2), "=r"(r3) : "r"(addr));
}
__device__ __forceinline__ void cpasync16(uint32_t dst, const void* src) {
    asm volatile("cp.async.cg.shared.global [%0], [%1], 16;" :: "r"(dst), "l"(src));
}
__device__ __forceinline__ void cp_commit() { asm volatile("cp.async.commit_group;"); }
template <int N> __device__ __forceinline__ void cp_wait() {
    asm volatile("cp.async.wait_group %0;" :: "n"(N));
}

// ---------------- bf16 TC GEMM: C = alpha*A*B^T + bias -------------------------
// A: MxK bf16 row-major ld=lda. B: NxK bf16 row-major ld=ldb.
// C: MxN (fp32 or bf16 by OUT_BF). 256 thr, 8 warps 4x2, warp tile 32x64,
// BK=32, 4-stage cp.async.  REQUIRES M%128==0, N%128==0, K%32==0, K>=128.
#define BK_     32
#define ASTR_   40                         // bf16 units per smem row (80B, conflict-free)
#define TILEB_  (128 * ASTR_ * 2)          // bytes per A (or B) tile = 10240
#define STGB_   (2 * TILEB_)               // bytes per stage = 20480
#define STG_    4
#define GEMM_SMEM (STG_ * STGB_)           // 81920

template <int OUT_BF>
__global__ void __launch_bounds__(256, 2)
gemm_bf(const bf16* __restrict__ A, const bf16* __restrict__ Bm,
        const float* __restrict__ bias, void* __restrict__ Cv,
        int M, int N, int K, float alpha, int lda, int ldb,
        ll saO, ll saI, int innerCnt, ll sbO, ll sbI, ll sC)
{
    extern __shared__ char sm[];
    const int z = blockIdx.z;
    const bf16* Ab = A + (ll)(z / innerCnt) * saO + (ll)(z % innerCnt) * saI
                       + (ll)blockIdx.y * 128 * lda;
    const bf16* Bb = Bm + (ll)(z / innerCnt) * sbO + (ll)(z % innerCnt) * sbI
                       + (ll)blockIdx.x * 128 * ldb;

    const int tid = threadIdx.x, lane = tid & 31, warp = tid >> 5;
    const int wm = (warp & 3) * 32, wn = (warp >> 2) * 64;
    const uint32_t smemBase = (uint32_t)__cvta_generic_to_shared(sm);

    // cp.async: 128 rows x 4 chunks(16B) per tile; 256 thr -> 2 chunks each
    const int ldRow = tid >> 2;            // 0..63
    const int ldChunk = tid & 3;           // 0..3
    const bf16* aSrc0 = Ab + (ll)ldRow * lda + ldChunk * 8;
    const bf16* aSrc1 = Ab + (ll)(ldRow + 64) * lda + ldChunk * 8;
    const bf16* bSrc0 = Bb + (ll)ldRow * ldb + ldChunk * 8;
    const bf16* bSrc1 = Bb + (ll)(ldRow + 64) * ldb + ldChunk * 8;
    const uint32_t dA0 = smemBase + (uint32_t)(ldRow * 80 + ldChunk * 16);
    const uint32_t dA1 = dA0 + 64u * 80u;
    const uint32_t dB0 = dA0 + (uint32_t)TILEB_;
    const uint32_t dB1 = dB0 + 64u * 80u;

    // ldmatrix fragment byte offsets within a stage
    const int laneRow = lane & 15;
    const int kHalf = (lane >> 4) << 3;    // 0 or 8 (bf16 units)
    uint32_t aOff[2], bOff[4];
#pragma unroll
    for (int mt = 0; mt < 2; mt++)
        aOff[mt] = (uint32_t)(((wm + mt * 16 + laneRow) * ASTR_ + kHalf) * 2);
#pragma unroll
    for (int np = 0; np < 4; np++)
        bOff[np] = (uint32_t)(TILEB_ + ((wn + np * 16 + laneRow) * ASTR_ + kHalf) * 2);

    float acc[2][8][4];
#pragma unroll
    for (int mt = 0; mt < 2; mt++)
#pragma unroll
        for (int nt = 0; nt < 8; nt++)
#pragma unroll
            for (int i = 0; i < 4; i++) acc[mt][nt][i] = 0.f;

    const int kTiles = K >> 5;

#pragma unroll
    for (int s = 0; s < STG_ - 1; s++) {
        const uint32_t so = (uint32_t)(s * STGB_);
        cpasync16(dA0 + so, aSrc0 + s * BK_);
        cpasync16(dA1 + so, aSrc1 + s * BK_);
        cpasync16(dB0 + so, bSrc0 + s * BK_);
        cpasync16(dB1 + so, bSrc1 + s * BK_);
        cp_commit();
    }

    for (int kt = 0; kt < kTiles; kt++) {
        cp_wait<STG_ - 2>();
        __syncthreads();

        if (kt + STG_ - 1 < kTiles) {
            const int s = kt + STG_ - 1;
            const uint32_t so = (uint32_t)((s & (STG_ - 1)) * STGB_);
            cpasync16(dA0 + so, aSrc0 + s * BK_);
            cpasync16(dA1 + so, aSrc1 + s * BK_);
            cpasync16(dB0 + so, bSrc0 + s * BK_);
            cpasync16(dB1 + so, bSrc1 + s * BK_);
        }
        cp_commit();

        const uint32_t slotB = smemBase + (uint32_t)((kt & (STG_ - 1)) * STGB_);
#pragma unroll
        for (int ks = 0; ks < 2; ks++) {           // two k16 sub-steps
            const uint32_t kb = (uint32_t)(ks * 32);   // 16 bf16 = 32 bytes
            uint32_t afr[2][4], bfr[4][4];
#pragma unroll
            for (int mt = 0; mt < 2; mt++)
                ldsm4(afr[mt][0], afr[mt][1], afr[mt][2], afr[mt][3],
                      slotB + aOff[mt] + kb);
#pragma unroll
            for (int np = 0; np < 4; np++)
                ldsm4(bfr[np][0], bfr[np][1], bfr[np][2], bfr[np][3],
                      slotB + bOff[np] + kb);
#pragma unroll
            for (int mt = 0; mt < 2; mt++)
#pragma unroll
                for (int np = 0; np < 4; np++) {
                    mma_bf16(acc[mt][2 * np][0], acc[mt][2 * np][1],
                             acc[mt][2 * np][2], acc[mt][2 * np][3],
                             afr[mt][0], afr[mt][1], afr[mt][2], afr[mt][3],
                             bfr[np][0], bfr[np][2]);
                    mma_bf16(acc[mt][2 * np + 1][0], acc[mt][2 * np + 1][1],
                             acc[mt][2 * np + 1][2], acc[mt][2 * np + 1][3],
                             afr[mt][0], afr[mt][1], afr[mt][2], afr[mt][3],
                             bfr[np][1], bfr[np][3]);
                }
        }
    }

    const int g = lane >> 2, tg = lane & 3;
#pragma unroll
    for (int mt = 0; mt < 2; mt++) {
        const int r0 = blockIdx.y * 128 + wm + mt * 16 + g;
#pragma unroll
        for (int nt = 0; nt < 8; nt++) {
            const int col = blockIdx.x * 128 + wn + nt * 8 + tg * 2;
            float2 bv = make_float2(0.f, 0.f);
            if (bias) bv = *(const float2*)&bias[col];
#pragma unroll
            for (int h = 0; h < 2; h++) {
                const int row = r0 + h * 8;
                float ox = alpha * acc[mt][nt][2 * h]     + bv.x;
                float oy = alpha * acc[mt][nt][2 * h + 1] + bv.y;
                if (OUT_BF) {
                    bf16* Cb = (bf16*)Cv + (ll)z * sC;
                    __nv_bfloat162 p;
                    p.x = __float2bfloat16_rn(ox);
                    p.y = __float2bfloat16_rn(oy);
                    *(__nv_bfloat162*)(Cb + (ll)row * N + col) = p;
                } else {
                    float* Cb = (float*)Cv + (ll)z * sC;
                    *(float2*)(Cb + (ll)row * N + col) = make_float2(ox, oy);
                }
            }
        }
    }
}

// ---------------- fp32 -> bf16 convert ----------------------------------------
__global__ void cvt_kernel(const float* __restrict__ in, bf16* __restrict__ out, ll n4)
{
    const ll i = (ll)blockIdx.x * blockDim.x + threadIdx.x;
    if (i >= n4) return;
    float4 v = ((const float4*)in)[i];
    ushort4 o;
    o.x = __bfloat16_as_ushort(__float2bfloat16_rn(v.x));
    o.y = __bfloat16_as_ushort(__float2bfloat16_rn(v.y));
    o.z = __bfloat16_as_ushort(__float2bfloat16_rn(v.z));
    o.w = __bfloat16_as_ushort(__float2bfloat16_rn(v.w));
    ((ushort4*)out)[i] = o;
}

// ---------------- transpose fp32 -> bf16 (weights) -----------------------------
__global__ void transpose_cvt_kernel(const float* __restrict__ in, bf16* __restrict__ out,
                                     int R, int C)
{
    __shared__ float t[32][33];
    const int c0 = blockIdx.x * 32, r0 = blockIdx.y * 32;
#pragma unroll
    for (int i = threadIdx.y; i < 32; i += 8)
        t[i][threadIdx.x] = in[(ll)(r0 + i) * C + c0 + threadIdx.x];
    __syncthreads();
#pragma unroll
    for (int i = threadIdx.y; i < 32; i += 8)
        out[(ll)(c0 + i) * R + r0 + threadIdx.x] = __float2bfloat16_rn(t[threadIdx.x][i]);
}

// ---------------- transpose bf16 -> bf16 (V buffers, batched) ------------------
__global__ void transpose_bf_kernel(const bf16* __restrict__ in, bf16* __restrict__ out,
                                    int R, int C)
{
    __shared__ bf16 t[32][33];
    const int z = blockIdx.z;
    const bf16* ib = in + (ll)z * R * C;
    bf16* ob = out + (ll)z * R * C;
    const int c0 = blockIdx.x * 32, r0 = blockIdx.y * 32;
#pragma unroll
    for (int i = threadIdx.y; i < 32; i += 8)
        t[i][threadIdx.x] = ib[(ll)(r0 + i) * C + c0 + threadIdx.x];
    __syncthreads();
#pragma unroll
    for (int i = threadIdx.y; i < 32; i += 8)
        ob[(ll)(c0 + i) * R + r0 + threadIdx.x] = t[threadIdx.x][i];
}

// ---------------- gates + selection scores (pure fp32) -------------------------
__global__ void gates_scores_kernel(const float* __restrict__ x,
                                    const float* __restrict__ Wg, const float* __restrict__ bg,
                                    const float* __restrict__ Ws, const float* __restrict__ bs,
                                    float* __restrict__ gates, float* __restrict__ scores)
{
    const int row = blockIdx.x * (blockDim.x >> 5) + (threadIdx.x >> 5);
    const int lane = threadIdx.x & 31;
    if (row >= B_ * L_) return;
    const float* xr = x + (ll)row * H_;
    float a0 = 0.f, a1 = 0.f, a2 = 0.f, a3 = 0.f;
    for (int k = lane; k < H_; k += 32) {
        const float xv = xr[k];
        a0 += xv * Wg[k * 3 + 0];
        a1 += xv * Wg[k * 3 + 1];
        a2 += xv * Wg[k * 3 + 2];
        a3 += xv * Ws[k];
    }
#pragma unroll
    for (int o = 16; o > 0; o >>= 1) {
        a0 += __shfl_down_sync(0xffffffffu, a0, o);
        a1 += __shfl_down_sync(0xffffffffu, a1, o);
        a2 += __shfl_down_sync(0xffffffffu, a2, o);
        a3 += __shfl_down_sync(0xffffffffu, a3, o);
    }
    if (lane == 0) {
        float s0 = 1.f / (1.f + expf(-(a0 + bg[0])));
        float s1 = 1.f / (1.f + expf(-(a1 + bg[1])));
        float s2 = 1.f / (1.f + expf(-(a2 + bg[2])));
        float inv = 1.f / (s0 + s1 + s2 + 1e-6f);
        gates[row * 3 + 0] = s0 * inv;
        gates[row * 3 + 1] = s1 * inv;
        gates[row * 3 + 2] = s2 * inv;
        scores[row] = a3 + bs[0];
    }
}

// ---------------- top-512 per batch --------------------------------------------
__global__ void topk_kernel(const float* __restrict__ scores, int* __restrict__ idx_out)
{
    __shared__ float sv[L_];
    __shared__ int   si[L_];
    __shared__ int   top[KSEL_];
    const int b = blockIdx.x;
    const float* s = scores + (ll)b * L_;
    for (int i = threadIdx.x; i < L_; i += blockDim.x) { sv[i] = s[i]; si[i] = i; }
    __syncthreads();
    for (int k = 2; k <= L_; k <<= 1)
        for (int j = k >> 1; j > 0; j >>= 1) {
            for (int i = threadIdx.x; i < L_; i += blockDim.x) {
                const int ixj = i ^ j;
                if (ixj > i) {
                    const bool desc = ((i & k) == 0);
                    const float a = sv[i], c = sv[ixj];
                    const bool sw = desc ? (a < c) : (a > c);
                    if (sw) {
                        sv[i] = c; sv[ixj] = a;
                        const int t = si[i]; si[i] = si[ixj]; si[ixj] = t;
                    }
                }
            }
            __syncthreads();
        }
    for (int i = threadIdx.x; i < KSEL_; i += blockDim.x) top[i] = si[i];
    __syncthreads();
    for (int k = 2; k <= KSEL_; k <<= 1)
        for (int j = k >> 1; j > 0; j >>= 1) {
            for (int i = threadIdx.x; i < KSEL_; i += blockDim.x) {
                const int ixj = i ^ j;
                if (ixj > i) {
                    const bool asc = ((i & k) == 0);
                    const int a = top[i], c = top[ixj];
                    const bool sw = asc ? (a > c) : (a < c);
                    if (sw) { top[i] = c; top[ixj] = a; }
                }
            }
            __syncthreads();
        }
    for (int i = threadIdx.x; i < KSEL_; i += blockDim.x) idx_out[b * KSEL_ + i] = top[i];
}

// ---------------- gather selected rows (bf16, vectorized) ----------------------
__global__ void gather_kernel(const bf16* __restrict__ Q, const bf16* __restrict__ K,
                              const bf16* __restrict__ V, const int* __restrict__ idx,
                              bf16* __restrict__ Qs, bf16* __restrict__ Ks, bf16* __restrict__ Vs)
{
    const int b = blockIdx.y, r = blockIdx.x;
    const int src = idx[b * KSEL_ + r];
    const ll so = ((ll)b * L_ + src) * H_ / 8;     // uint4 units
    const ll dst = ((ll)b * KSEL_ + r) * H_ / 8;
    const int i = threadIdx.x;                      // 128 threads, H_/8 = 128
    ((uint4*)Qs)[dst + i] = ((const uint4*)Q)[so + i];
    ((uint4*)Ks)[dst + i] = ((const uint4*)K)[so + i];
    ((uint4*)Vs)[dst + i] = ((const uint4*)V)[so + i];
}

// ---------------- row softmax: fp32 in -> bf16 out ------------------------------
__global__ void softmax_kernel(const float* __restrict__ S, bf16* __restrict__ P, int n)
{
    const ll row = blockIdx.x;
    const float* s = S + row * (ll)n;
    bf16* p = P + row * (ll)n;
    const int tid = threadIdx.x;
    __shared__ float red[32];
    __shared__ float bc;

    float m = -1e30f;
    for (int i = tid; i < n; i += blockDim.x) m = fmaxf(m, s[i]);
#pragma unroll
    for (int o = 16; o > 0; o >>= 1) m = fmaxf(m, __shfl_xor_sync(0xffffffffu, m, o));
    if ((tid & 31) == 0) red[tid >> 5] = m;
    __syncthreads();
    if (tid == 0) {
        float mm = -1e30f;
        for (int i = 0; i < (int)(blockDim.x >> 5); i++) mm = fmaxf(mm, red[i]);
        bc = mm;
    }
    __syncthreads();
    m = bc;
    __syncthreads();

    float sum = 0.f;
    for (int i = tid; i < n; i += blockDim.x) sum += expf(s[i] - m);
#pragma unroll
    for (int o = 16; o > 0; o >>= 1) sum += __shfl_xor_sync(0xffffffffu, sum, o);
    if ((tid & 31) == 0) red[tid >> 5] = sum;
    __syncthreads();
    if (tid == 0) {
        float ss = 0.f;
        for (int i = 0; i < (int)(blockDim.x >> 5); i++) ss += red[i];
        bc = 1.f / ss;
    }
    __syncthreads();
    const float inv = bc;
    for (int i = tid; i < n; i += blockDim.x)
        p[i] = __float2bfloat16_rn(expf(s[i] - m) * inv);
}

// ---------------- assemble gated combined (fp32 in -> bf16 out) -----------------
__global__ void assemble_kernel(const float* __restrict__ comp_out, const float* __restrict__ sel_out,
                                const float* __restrict__ win_out, const float* __restrict__ gates,
                                bf16* __restrict__ comb)
{
    const ll t = blockIdx.x;
    const int b = (int)(t >> 12), l = (int)(t & 4095);
    const float g0 = gates[t * 3 + 0], g1 = gates[t * 3 + 1], g2 = gates[t * 3 + 2];
    bf16* c = comb + t * (ll)(3 * H_);
    const float* co = comp_out + ((ll)b * LC_ + l) * H_;
    const float* so = sel_out + ((ll)b * KSEL_ + l) * H_;
    const float* wo = win_out + t * (ll)H_;
    const bool hasC = (l < LC_), hasS = (l < KSEL_);
    for (int i = threadIdx.x; i < H_; i += blockDim.x) {
        c[i]          = __float2bfloat16_rn(hasC ? co[i] * g0 : 0.f);
        c[H_ + i]     = __float2bfloat16_rn(hasS ? so[i] * g1 : 0.f);
        c[2 * H_ + i] = __float2bfloat16_rn(wo[i] * g2);
    }
}

// ---------------- residual + layernorm ------------------------------------------
__global__ void final_ln_kernel(const float* __restrict__ pre, const float* __restrict__ x,
                                float* __restrict__ out)
{
    const ll row = blockIdx.x;
    const float* p = pre + row * (ll)H_;
    const float* xr = x + row * (ll)H_;
    float* o = out + row * (ll)H_;
    const int tid = threadIdx.x;
    __shared__ float buf[H_];
    __shared__ float red[64];
    __shared__ float stats[2];

    float s = 0.f, ss = 0.f;
    for (int i = tid; i < H_; i += blockDim.x) {
        const float v = 0.5f * (p[i] + xr[i]);
        buf[i] = v;
        s += v;
        ss += v * v;
    }
#pragma unroll
    for (int o2 = 16; o2 > 0; o2 >>= 1) {
        s  += __shfl_xor_sync(0xffffffffu, s, o2);
        ss += __shfl_xor_sync(0xffffffffu, ss, o2);
    }
    if ((tid & 31) == 0) { red[tid >> 5] = s; red[32 + (tid >> 5)] = ss; }
    __syncthreads();
    if (tid == 0) {
        float ts = 0.f, tss = 0.f;
        for (int i = 0; i < (int)(blockDim.x >> 5); i++) { ts += red[i]; tss += red[32 + i]; }
        const float mean = ts / (float)H_;
        const float var = tss / (float)H_ - mean * mean;
        stats[0] = mean;
        stats[1] = rsqrtf(var + 1e-6f);
    }
    __syncthreads();
    const float mean = stats[0], inv = stats[1];
    for (int i = tid; i < H_; i += blockDim.x) o[i] = (buf[i] - mean) * inv;
}

// ------------------------------- launcher ----------------------------------------
extern "C" void kernel_launch(void* const* d_in, const int* in_sizes, int n_in,
                              void* d_out, int out_size)
{
    const float* x  = (const float*)d_in[0];
    const float* Wq = (const float*)d_in[1];
    const float* bq = (const float*)d_in[2];
    const float* Wk = (const float*)d_in[3];
    const float* bk = (const float*)d_in[4];
    const float* Wv = (const float*)d_in[5];
    const float* bv = (const float*)d_in[6];
    const float* Wo = (const float*)d_in[7];
    const float* bo = (const float*)d_in[8];
    const float* Wg = (const float*)d_in[9];
    const float* bg = (const float*)d_in[10];
    const float* Wc = (const float*)d_in[11];
    const float* bc = (const float*)d_in[12];
    const float* Ws = (const float*)d_in[13];
    const float* bs = (const float*)d_in[14];
    float* out = (float*)d_out;

    bf16 *xh, *Q, *K, *V, *VT, *cmp, *Qc, *Kc, *Vc, *VcT, *P;
    bf16 *Qs, *Ks, *Vs, *VsT, *comb, *WqT, *WkT, *WvT, *WcT, *WoT;
    float *S, *comp_out, *sel_out, *win_out, *pre, *gates, *scores;
    int* idx;
    cudaGetSymbolAddress((void**)&xh, g_xh);
    cudaGetSymbolAddress((void**)&Q, g_Q);
    cudaGetSymbolAddress((void**)&K, g_Kb);
    cudaGetSymbolAddress((void**)&V, g_Vb);
    cudaGetSymbolAddress((void**)&VT, g_VT);
    cudaGetSymbolAddress((void**)&cmp, g_cmp);
    cudaGetSymbolAddress((void**)&Qc, g_Qc);
    cudaGetSymbolAddress((void**)&Kc, g_Kc);
    cudaGetSymbolAddress((void**)&Vc, g_Vc);
    cudaGetSymbolAddress((void**)&VcT, g_VcT);
    cudaGetSymbolAddress((void**)&S, g_S);
    cudaGetSymbolAddress((void**)&P, g_P);
    cudaGetSymbolAddress((void**)&comp_out, g_comp_out);
    cudaGetSymbolAddress((void**)&Qs, g_Qs);
    cudaGetSymbolAddress((void**)&Ks, g_Ks);
    cudaGetSymbolAddress((void**)&Vs, g_Vs);
    cudaGetSymbolAddress((void**)&VsT, g_VsT);
    cudaGetSymbolAddress((void**)&sel_out, g_sel_out);
    cudaGetSymbolAddress((void**)&win_out, g_win_out);
    cudaGetSymbolAddress((void**)&comb, g_comb);
    cudaGetSymbolAddress((void**)&pre, g_pre);
    cudaGetSymbolAddress((void**)&gates, g_gates);
    cudaGetSymbolAddress((void**)&scores, g_scores);
    cudaGetSymbolAddress((void**)&idx, g_idx);
    cudaGetSymbolAddress((void**)&WqT, g_WqT);
    cudaGetSymbolAddress((void**)&WkT, g_WkT);
    cudaGetSymbolAddress((void**)&WvT, g_WvT);
    cudaGetSymbolAddress((void**)&WcT, g_WcT);
    cudaGetSymbolAddress((void**)&WoT, g_WoT);

    cudaFuncSetAttribute(gemm_bf<0>, cudaFuncAttributeMaxDynamicSharedMemorySize, GEMM_SMEM);
    cudaFuncSetAttribute(gemm_bf<1>, cudaFuncAttributeMaxDynamicSharedMemorySize, GEMM_SMEM);

    const int MT = B_ * L_;
    const dim3 tb(32, 8);

    gates_scores_kernel<<<MT / 8, 256>>>(x, Wg, bg, Ws, bs, gates, scores);

    // convert x; transpose+convert weights
    cvt_kernel<<<(unsigned)(((ll)MT * H_ / 4 + 255) / 256), 256>>>(x, xh, (ll)MT * H_ / 4);
    transpose_cvt_kernel<<<dim3(H_ / 32, H_ / 32), tb>>>(Wq, WqT, H_, H_);
    transpose_cvt_kernel<<<dim3(H_ / 32, H_ / 32), tb>>>(Wk, WkT, H_, H_);
    transpose_cvt_kernel<<<dim3(H_ / 32, H_ / 32), tb>>>(Wv, WvT, H_, H_);
    transpose_cvt_kernel<<<dim3(H_ / 32, (4 * H_) / 32), tb>>>(Wc, WcT, 4 * H_, H_);
    transpose_cvt_kernel<<<dim3(H_ / 32, (3 * H_) / 32), tb>>>(Wo, WoT, 3 * H_, H_);

    // full-sequence QKV (bf16 out)
    {
        dim3 g(H_ / 128, MT / 128, 1);
        gemm_bf<1><<<g, 256, GEMM_SMEM>>>(xh, WqT, bq, Q, MT, H_, H_, 1.f, H_, H_, 0, 0, 1, 0, 0, 0);
        gemm_bf<1><<<g, 256, GEMM_SMEM>>>(xh, WkT, bk, K, MT, H_, H_, 1.f, H_, H_, 0, 0, 1, 0, 0, 0);
        gemm_bf<1><<<g, 256, GEMM_SMEM>>>(xh, WvT, bv, V, MT, H_, H_, 1.f, H_, H_, 0, 0, 1, 0, 0, 0);
    }
    transpose_bf_kernel<<<dim3(H_ / 32, L_ / 32, B_), tb>>>(V, VT, L_, H_);

    // compressed branch projections
    {
        dim3 g(H_ / 128, (B_ * LC_) / 128, 1);
        gemm_bf<1><<<g, 256, GEMM_SMEM>>>(xh, WcT, bc, cmp, B_ * LC_, H_, 4 * H_, 1.f, 4 * H_, 4 * H_, 0, 0, 1, 0, 0, 0);
        gemm_bf<1><<<g, 256, GEMM_SMEM>>>(cmp, WqT, bq, Qc, B_ * LC_, H_, H_, 1.f, H_, H_, 0, 0, 1, 0, 0, 0);
        gemm_bf<1><<<g, 256, GEMM_SMEM>>>(cmp, WkT, bk, Kc, B_ * LC_, H_, H_, 1.f, H_, H_, 0, 0, 1, 0, 0, 0);
        gemm_bf<1><<<g, 256, GEMM_SMEM>>>(cmp, WvT, bv, Vc, B_ * LC_, H_, H_, 1.f, H_, H_, 0, 0, 1, 0, 0, 0);
    }
    transpose_bf_kernel<<<dim3(H_ / 32, LC_ / 32, B_), tb>>>(Vc, VcT, LC_, H_);

    topk_kernel<<<B_, 512>>>(scores, idx);
    gather_kernel<<<dim3(KSEL_, B_), 128>>>(Q, K, V, idx, Qs, Ks, Vs);
    transpose_bf_kernel<<<dim3(H_ / 32, KSEL_ / 32, B_), tb>>>(Vs, VsT, KSEL_, H_);

    // compressed attention
    gemm_bf<0><<<dim3(LC_ / 128, LC_ / 128, B_), 256, GEMM_SMEM>>>(
        Qc, Kc, nullptr, S, LC_, LC_, H_, SCALE_, H_, H_,
        (ll)LC_ * H_, 0, 1, (ll)LC_ * H_, 0, (ll)LC_ * LC_);
    softmax_kernel<<<B_ * LC_, 256>>>(S, P, LC_);
    gemm_bf<0><<<dim3(H_ / 128, LC_ / 128, B_), 256, GEMM_SMEM>>>(
        P, VcT, nullptr, comp_out, LC_, H_, LC_, 1.f, LC_, LC_,
        (ll)LC_ * LC_, 0, 1, (ll)H_ * LC_, 0, (ll)LC_ * H_);

    // selected attention
    gemm_bf<0><<<dim3(KSEL_ / 128, KSEL_ / 128, B_), 256, GEMM_SMEM>>>(
        Qs, Ks, nullptr, S, KSEL_, KSEL_, H_, SCALE_, H_, H_,
        (ll)KSEL_ * H_, 0, 1, (ll)KSEL_ * H_, 0, (ll)KSEL_ * KSEL_);
    softmax_kernel<<<B_ * KSEL_, 256>>>(S, P, KSEL_);
    gemm_bf<0><<<dim3(H_ / 128, KSEL_ / 128, B_), 256, GEMM_SMEM>>>(
        P, VsT, nullptr, sel_out, KSEL_, H_, KSEL_, 1.f, KSEL_, KSEL_,
        (ll)KSEL_ * KSEL_, 0, 1, (ll)H_ * KSEL_, 0, (ll)KSEL_ * H_);

    // window attention
    gemm_bf<0><<<dim3(WIN_ / 128, WIN_ / 128, B_ * NW_), 256, GEMM_SMEM>>>(
        Q, K, nullptr, S, WIN_, WIN_, H_, SCALE_, H_, H_,
        (ll)L_ * H_, (ll)128 * H_, NW_,
        (ll)L_ * H_, (ll)128 * H_, (ll)WIN_ * WIN_);
    softmax_kernel<<<B_ * NW_ * WIN_, 256>>>(S, P, WIN_);
    gemm_bf<0><<<dim3(H_ / 128, WIN_ / 128, B_ * NW_), 256, GEMM_SMEM>>>(
        P, VT, nullptr, win_out, WIN_, H_, WIN_, 1.f, WIN_, L_,
        (ll)NW_ * WIN_ * WIN_, (ll)WIN_ * WIN_, NW_,
        (ll)H_ * L_, 128, (ll)WIN_ * H_);

    assemble_kernel<<<MT, 256>>>(comp_out, sel_out, win_out, gates, comb);
    gemm_bf<0><<<dim3(H_ / 128, MT / 128, 1), 256, GEMM_SMEM>>>(
        comb, WoT, bo, pre, MT, H_, 3 * H_, 1.f, 3 * H_, 3 * H_, 0, 0, 1, 0, 0, 0);
    final_ln_kernel<<<MT, 256>>>(pre, x, out);
}

// round 8
// speedup vs baseline: 3.2387x; 1.2115x over previous
#include <cuda_runtime.h>
#include <cuda_bf16.h>
#include <math.h>
#include <stdint.h>

#define B_    4
#define L_    4096
#define H_    1024
#define LC_   1024
#define KSEL_ 512
#define WIN_  256
#define NW_   16
#define SCALE_ 0.125f

typedef long long ll;
typedef __nv_bfloat16 bf16;

// ---------------- scratch -----------------------------------------------------
__device__ bf16  g_xh[(size_t)B_ * L_ * H_];
__device__ bf16  g_Q[(size_t)B_ * L_ * H_];
__device__ bf16  g_Kb[(size_t)B_ * L_ * H_];
__device__ bf16  g_Vb[(size_t)B_ * L_ * H_];
__device__ bf16  g_VT[(size_t)B_ * H_ * L_];
__device__ bf16  g_cmp[(size_t)B_ * LC_ * H_];
__device__ bf16  g_Qc[(size_t)B_ * LC_ * H_];
__device__ bf16  g_Kc[(size_t)B_ * LC_ * H_];
__device__ bf16  g_Vc[(size_t)B_ * LC_ * H_];
__device__ bf16  g_VcT[(size_t)B_ * H_ * LC_];
__device__ float g_S[(size_t)B_ * LC_ * LC_];
__device__ bf16  g_P[(size_t)B_ * LC_ * LC_];
__device__ bf16  g_comp_g[(size_t)B_ * LC_ * H_];
__device__ bf16  g_Qs[(size_t)B_ * KSEL_ * H_];
__device__ bf16  g_Ks[(size_t)B_ * KSEL_ * H_];
__device__ bf16  g_Vs[(size_t)B_ * KSEL_ * H_];
__device__ bf16  g_VsT[(size_t)B_ * H_ * KSEL_];
__device__ bf16  g_sel_g[(size_t)B_ * KSEL_ * H_];
__device__ bf16  g_win_g[(size_t)B_ * L_ * H_];
__device__ float g_pre[(size_t)B_ * L_ * H_];
__device__ float g_gates[(size_t)B_ * L_ * 3];
__device__ float g_scores[(size_t)B_ * L_];
__device__ int   g_idx[B_ * KSEL_];
__device__ bf16  g_WqT[(size_t)H_ * H_];
__device__ bf16  g_WkT[(size_t)H_ * H_];
__device__ bf16  g_WvT[(size_t)H_ * H_];
__device__ bf16  g_WcT[(size_t)4 * H_ * H_];
__device__ bf16  g_WoT[(size_t)3 * H_ * H_];     // 1024 x 3072, ld 3072

// ---------------- asm helpers --------------------------------------------------
__device__ __forceinline__ void mma_bf16(float& c0, float& c1, float& c2, float& c3,
                                         uint32_t a0, uint32_t a1, uint32_t a2, uint32_t a3,
                                         uint32_t b0, uint32_t b1) {
    asm volatile(
        "mma.sync.aligned.m16n8k16.row.col.f32.bf16.bf16.f32 "
        "{%0,%1,%2,%3}, {%4,%5,%6,%7}, {%8,%9}, {%0,%1,%2,%3};"
        : "+f"(c0), "+f"(c1), "+f"(c2), "+f"(c3)
        : "r"(a0), "r"(a1), "r"(a2), "r"(a3), "r"(b0), "r"(b1));
}
__device__ __forceinline__ void ldsm4(uint32_t& r0, uint32_t& r1, uint32_t& r2, uint32_t& r3,
                                      uint32_t addr) {
    asm volatile("ldmatrix.sync.aligned.m8n8.x4.shared.b16 {%0,%1,%2,%3}, [%4];"
                 : "=r"(r0), "=r"(r1), "=r"(r2), "=r"(r3) : "r"(addr));
}
__device__ __forceinline__ void cpasync16(uint32_t dst, const void* src) {
    asm volatile("cp.async.cg.shared.global [%0], [%1], 16;" :: "r"(dst), "l"(src));
}
__device__ __forceinline__ void cp_commit() { asm volatile("cp.async.commit_group;"); }
template <int N> __device__ __forceinline__ void cp_wait() {
    asm volatile("cp.async.wait_group %0;" :: "n"(N));
}

// ---------------- bf16 TC GEMM: C = alpha*A*B^T*(rowScale) + bias (+C) ----------
// A: MxK bf16 row-major ld=lda. B: NxK bf16 row-major ld=ldb.
// OUT_BF: C dtype bf16 else fp32. ACC: C += result. rs: optional per-row scale
// (stride 3), rs_row_base = rs + (z/inner)*rsO + (z%inner)*rsI.
// 256 thr, 8 warps 4x2, warp tile 32x64, BK=32, 4-stage cp.async.
// REQUIRES M%128==0, N%128==0, K%32==0, K>=128.
#define BK_     32
#define ASTR_   40
#define TILEB_  (128 * ASTR_ * 2)
#define STGB_   (2 * TILEB_)
#define STG_    4
#define GEMM_SMEM (STG_ * STGB_)

template <int OUT_BF, int ACC>
__global__ void __launch_bounds__(256, 2)
gemm_bf(const bf16* __restrict__ A, const bf16* __restrict__ Bm,
        const float* __restrict__ bias, const float* __restrict__ rs,
        ll rsO, ll rsI, void* __restrict__ Cv,
        int M, int N, int K, float alpha, int lda, int ldb,
        ll saO, ll saI, int innerCnt, ll sbO, ll sbI, ll sC)
{
    extern __shared__ char sm[];
    const int z = blockIdx.z;
    const bf16* Ab = A + (ll)(z / innerCnt) * saO + (ll)(z % innerCnt) * saI
                       + (ll)blockIdx.y * 128 * lda;
    const bf16* Bb = Bm + (ll)(z / innerCnt) * sbO + (ll)(z % innerCnt) * sbI
                       + (ll)blockIdx.x * 128 * ldb;

    const int tid = threadIdx.x, lane = tid & 31, warp = tid >> 5;
    const int wm = (warp & 3) * 32, wn = (warp >> 2) * 64;
    const uint32_t smemBase = (uint32_t)__cvta_generic_to_shared(sm);

    const int ldRow = tid >> 2;
    const int ldChunk = tid & 3;
    const bf16* aSrc0 = Ab + (ll)ldRow * lda + ldChunk * 8;
    const bf16* aSrc1 = Ab + (ll)(ldRow + 64) * lda + ldChunk * 8;
    const bf16* bSrc0 = Bb + (ll)ldRow * ldb + ldChunk * 8;
    const bf16* bSrc1 = Bb + (ll)(ldRow + 64) * ldb + ldChunk * 8;
    const uint32_t dA0 = smemBase + (uint32_t)(ldRow * 80 + ldChunk * 16);
    const uint32_t dA1 = dA0 + 64u * 80u;
    const uint32_t dB0 = dA0 + (uint32_t)TILEB_;
    const uint32_t dB1 = dB0 + 64u * 80u;

    const int laneRow = lane & 15;
    const int kHalf = (lane >> 4) << 3;
    uint32_t aOff[2], bOff[4];
#pragma unroll
    for (int mt = 0; mt < 2; mt++)
        aOff[mt] = (uint32_t)(((wm + mt * 16 + laneRow) * ASTR_ + kHalf) * 2);
#pragma unroll
    for (int np = 0; np < 4; np++)
        bOff[np] = (uint32_t)(TILEB_ + ((wn + np * 16 + laneRow) * ASTR_ + kHalf) * 2);

    float acc[2][8][4];
#pragma unroll
    for (int mt = 0; mt < 2; mt++)
#pragma unroll
        for (int nt = 0; nt < 8; nt++)
#pragma unroll
            for (int i = 0; i < 4; i++) acc[mt][nt][i] = 0.f;

    const int kTiles = K >> 5;

#pragma unroll
    for (int s = 0; s < STG_ - 1; s++) {
        const uint32_t so = (uint32_t)(s * STGB_);
        cpasync16(dA0 + so, aSrc0 + s * BK_);
        cpasync16(dA1 + so, aSrc1 + s * BK_);
        cpasync16(dB0 + so, bSrc0 + s * BK_);
        cpasync16(dB1 + so, bSrc1 + s * BK_);
        cp_commit();
    }

    for (int kt = 0; kt < kTiles; kt++) {
        cp_wait<STG_ - 2>();
        __syncthreads();

        if (kt + STG_ - 1 < kTiles) {
            const int s = kt + STG_ - 1;
            const uint32_t so = (uint32_t)((s & (STG_ - 1)) * STGB_);
            cpasync16(dA0 + so, aSrc0 + s * BK_);
            cpasync16(dA1 + so, aSrc1 + s * BK_);
            cpasync16(dB0 + so, bSrc0 + s * BK_);
            cpasync16(dB1 + so, bSrc1 + s * BK_);
        }
        cp_commit();

        const uint32_t slotB = smemBase + (uint32_t)((kt & (STG_ - 1)) * STGB_);
#pragma unroll
        for (int ks = 0; ks < 2; ks++) {
            const uint32_t kb = (uint32_t)(ks * 32);
            uint32_t afr[2][4], bfr[4][4];
#pragma unroll
            for (int mt = 0; mt < 2; mt++)
                ldsm4(afr[mt][0], afr[mt][1], afr[mt][2], afr[mt][3],
                      slotB + aOff[mt] + kb);
#pragma unroll
            for (int np = 0; np < 4; np++)
                ldsm4(bfr[np][0], bfr[np][1], bfr[np][2], bfr[np][3],
                      slotB + bOff[np] + kb);
#pragma unroll
            for (int mt = 0; mt < 2; mt++)
#pragma unroll
                for (int np = 0; np < 4; np++) {
                    mma_bf16(acc[mt][2 * np][0], acc[mt][2 * np][1],
                             acc[mt][2 * np][2], acc[mt][2 * np][3],
                             afr[mt][0], afr[mt][1], afr[mt][2], afr[mt][3],
                             bfr[np][0], bfr[np][2]);
                    mma_bf16(acc[mt][2 * np + 1][0], acc[mt][2 * np + 1][1],
                             acc[mt][2 * np + 1][2], acc[mt][2 * np + 1][3],
                             afr[mt][0], afr[mt][1], afr[mt][2], afr[mt][3],
                             bfr[np][1], bfr[np][3]);
                }
        }
    }

    const float* rsRow = rs ? rs + (z / innerCnt) * rsO + (z % innerCnt) * rsI : nullptr;
    const int g = lane >> 2, tg = lane & 3;
#pragma unroll
    for (int mt = 0; mt < 2; mt++) {
        const int rBase = blockIdx.y * 128 + wm + mt * 16 + g;
#pragma unroll
        for (int h = 0; h < 2; h++) {
            const int row = rBase + h * 8;
            const float scale = rsRow ? rsRow[(ll)row * 3] : 1.f;
#pragma unroll
            for (int nt = 0; nt < 8; nt++) {
                const int col = blockIdx.x * 128 + wn + nt * 8 + tg * 2;
                float2 bv = make_float2(0.f, 0.f);
                if (bias) bv = *(const float2*)&bias[col];
                float ox = alpha * acc[mt][nt][2 * h]     * scale + bv.x;
                float oy = alpha * acc[mt][nt][2 * h + 1] * scale + bv.y;
                if (OUT_BF) {
                    bf16* Cb = (bf16*)Cv + (ll)z * sC;
                    __nv_bfloat162 p;
                    p.x = __float2bfloat16_rn(ox);
                    p.y = __float2bfloat16_rn(oy);
                    *(__nv_bfloat162*)(Cb + (ll)row * N + col) = p;
                } else {
                    float* Cb = (float*)Cv + (ll)z * sC;
                    float2 o = make_float2(ox, oy);
                    if (ACC) {
                        float2 prev = *(float2*)(Cb + (ll)row * N + col);
                        o.x += prev.x; o.y += prev.y;
                    }
                    *(float2*)(Cb + (ll)row * N + col) = o;
                }
            }
        }
    }
}

// ---------------- fp32 -> bf16 convert ----------------------------------------
__global__ void cvt_kernel(const float* __restrict__ in, bf16* __restrict__ out, ll n4)
{
    const ll i = (ll)blockIdx.x * blockDim.x + threadIdx.x;
    if (i >= n4) return;
    float4 v = ((const float4*)in)[i];
    ushort4 o;
    o.x = __bfloat16_as_ushort(__float2bfloat16_rn(v.x));
    o.y = __bfloat16_as_ushort(__float2bfloat16_rn(v.y));
    o.z = __bfloat16_as_ushort(__float2bfloat16_rn(v.z));
    o.w = __bfloat16_as_ushort(__float2bfloat16_rn(v.w));
    ((ushort4*)out)[i] = o;
}

// ---------------- transpose fp32 -> bf16 (weights) -----------------------------
__global__ void transpose_cvt_kernel(const float* __restrict__ in, bf16* __restrict__ out,
                                     int R, int C)
{
    __shared__ float t[32][33];
    const int c0 = blockIdx.x * 32, r0 = blockIdx.y * 32;
#pragma unroll
    for (int i = threadIdx.y; i < 32; i += 8)
        t[i][threadIdx.x] = in[(ll)(r0 + i) * C + c0 + threadIdx.x];
    __syncthreads();
#pragma unroll
    for (int i = threadIdx.y; i < 32; i += 8)
        out[(ll)(c0 + i) * R + r0 + threadIdx.x] = __float2bfloat16_rn(t[threadIdx.x][i]);
}

// ---------------- transpose bf16 -> bf16 (batched) -----------------------------
__global__ void transpose_bf_kernel(const bf16* __restrict__ in, bf16* __restrict__ out,
                                    int R, int C)
{
    __shared__ bf16 t[32][33];
    const int z = blockIdx.z;
    const bf16* ib = in + (ll)z * R * C;
    bf16* ob = out + (ll)z * R * C;
    const int c0 = blockIdx.x * 32, r0 = blockIdx.y * 32;
#pragma unroll
    for (int i = threadIdx.y; i < 32; i += 8)
        t[i][threadIdx.x] = ib[(ll)(r0 + i) * C + c0 + threadIdx.x];
    __syncthreads();
#pragma unroll
    for (int i = threadIdx.y; i < 32; i += 8)
        ob[(ll)(c0 + i) * R + r0 + threadIdx.x] = t[threadIdx.x][i];
}

// ---------------- gates + selection scores (pure fp32) -------------------------
__global__ void gates_scores_kernel(const float* __restrict__ x,
                                    const float* __restrict__ Wg, const float* __restrict__ bg,
                                    const float* __restrict__ Ws, const float* __restrict__ bs,
                                    float* __restrict__ gates, float* __restrict__ scores)
{
    const int row = blockIdx.x * (blockDim.x >> 5) + (threadIdx.x >> 5);
    const int lane = threadIdx.x & 31;
    if (row >= B_ * L_) return;
    const float* xr = x + (ll)row * H_;
    float a0 = 0.f, a1 = 0.f, a2 = 0.f, a3 = 0.f;
    for (int k = lane; k < H_; k += 32) {
        const float xv = xr[k];
        a0 += xv * Wg[k * 3 + 0];
        a1 += xv * Wg[k * 3 + 1];
        a2 += xv * Wg[k * 3 + 2];
        a3 += xv * Ws[k];
    }
#pragma unroll
    for (int o = 16; o > 0; o >>= 1) {
        a0 += __shfl_down_sync(0xffffffffu, a0, o);
        a1 += __shfl_down_sync(0xffffffffu, a1, o);
        a2 += __shfl_down_sync(0xffffffffu, a2, o);
        a3 += __shfl_down_sync(0xffffffffu, a3, o);
    }
    if (lane == 0) {
        float s0 = 1.f / (1.f + expf(-(a0 + bg[0])));
        float s1 = 1.f / (1.f + expf(-(a1 + bg[1])));
        float s2 = 1.f / (1.f + expf(-(a2 + bg[2])));
        float inv = 1.f / (s0 + s1 + s2 + 1e-6f);
        gates[row * 3 + 0] = s0 * inv;
        gates[row * 3 + 1] = s1 * inv;
        gates[row * 3 + 2] = s2 * inv;
        scores[row] = a3 + bs[0];
    }
}

// ---------------- top-512 per batch --------------------------------------------
__global__ void topk_kernel(const float* __restrict__ scores, int* __restrict__ idx_out)
{
    __shared__ float sv[L_];
    __shared__ int   si[L_];
    __shared__ int   top[KSEL_];
    const int b = blockIdx.x;
    const float* s = scores + (ll)b * L_;
    for (int i = threadIdx.x; i < L_; i += blockDim.x) { sv[i] = s[i]; si[i] = i; }
    __syncthreads();
    for (int k = 2; k <= L_; k <<= 1)
        for (int j = k >> 1; j > 0; j >>= 1) {
            for (int i = threadIdx.x; i < L_; i += blockDim.x) {
                const int ixj = i ^ j;
                if (ixj > i) {
                    const bool desc = ((i & k) == 0);
                    const float a = sv[i], c = sv[ixj];
                    const bool sw = desc ? (a < c) : (a > c);
                    if (sw) {
                        sv[i] = c; sv[ixj] = a;
                        const int t = si[i]; si[i] = si[ixj]; si[ixj] = t;
                    }
                }
            }
            __syncthreads();
        }
    for (int i = threadIdx.x; i < KSEL_; i += blockDim.x) top[i] = si[i];
    __syncthreads();
    for (int k = 2; k <= KSEL_; k <<= 1)
        for (int j = k >> 1; j > 0; j >>= 1) {
            for (int i = threadIdx.x; i < KSEL_; i += blockDim.x) {
                const int ixj = i ^ j;
                if (ixj > i) {
                    const bool asc = ((i & k) == 0);
                    const int a = top[i], c = top[ixj];
                    const bool sw = asc ? (a > c) : (a < c);
                    if (sw) { top[i] = c; top[ixj] = a; }
                }
            }
            __syncthreads();
        }
    for (int i = threadIdx.x; i < KSEL_; i += blockDim.x) idx_out[b * KSEL_ + i] = top[i];
}

// ---------------- gather selected rows ------------------------------------------
__global__ void gather_kernel(const bf16* __restrict__ Q, const bf16* __restrict__ K,
                              const bf16* __restrict__ V, const int* __restrict__ idx,
                              bf16* __restrict__ Qs, bf16* __restrict__ Ks, bf16* __restrict__ Vs)
{
    const int b = blockIdx.y, r = blockIdx.x;
    const int src = idx[b * KSEL_ + r];
    const ll so = ((ll)b * L_ + src) * H_ / 8;
    const ll dst = ((ll)b * KSEL_ + r) * H_ / 8;
    const int i = threadIdx.x;
    ((uint4*)Qs)[dst + i] = ((const uint4*)Q)[so + i];
    ((uint4*)Ks)[dst + i] = ((const uint4*)K)[so + i];
    ((uint4*)Vs)[dst + i] = ((const uint4*)V)[so + i];
}

// ---------------- row softmax: fp32 in -> bf16 out -------------------------------
__global__ void softmax_kernel(const float* __restrict__ S, bf16* __restrict__ P, int n)
{
    const ll row = blockIdx.x;
    const float* s = S + row * (ll)n;
    bf16* p = P + row * (ll)n;
    const int tid = threadIdx.x;
    __shared__ float red[32];
    __shared__ float bc;

    float m = -1e30f;
    for (int i = tid; i < n; i += blockDim.x) m = fmaxf(m, s[i]);
#pragma unroll
    for (int o = 16; o > 0; o >>= 1) m = fmaxf(m, __shfl_xor_sync(0xffffffffu, m, o));
    if ((tid & 31) == 0) red[tid >> 5] = m;
    __syncthreads();
    if (tid == 0) {
        float mm = -1e30f;
        for (int i = 0; i < (int)(blockDim.x >> 5); i++) mm = fmaxf(mm, red[i]);
        bc = mm;
    }
    __syncthreads();
    m = bc;
    __syncthreads();

    float sum = 0.f;
    for (int i = tid; i < n; i += blockDim.x) sum += expf(s[i] - m);
#pragma unroll
    for (int o = 16; o > 0; o >>= 1) sum += __shfl_xor_sync(0xffffffffu, sum, o);
    if ((tid & 31) == 0) red[tid >> 5] = sum;
    __syncthreads();
    if (tid == 0) {
        float ss = 0.f;
        for (int i = 0; i < (int)(blockDim.x >> 5); i++) ss += red[i];
        bc = 1.f / ss;
    }
    __syncthreads();
    const float inv = bc;
    for (int i = tid; i < n; i += blockDim.x)
        p[i] = __float2bfloat16_rn(expf(s[i] - m) * inv);
}

// ---------------- residual + layernorm --------------------------------------------
__global__ void final_ln_kernel(const float* __restrict__ pre, const float* __restrict__ x,
                                float* __restrict__ out)
{
    const ll row = blockIdx.x;
    const float* p = pre + row * (ll)H_;
    const float* xr = x + row * (ll)H_;
    float* o = out + row * (ll)H_;
    const int tid = threadIdx.x;
    __shared__ float buf[H_];
    __shared__ float red[64];
    __shared__ float stats[2];

    float s = 0.f, ss = 0.f;
    for (int i = tid; i < H_; i += blockDim.x) {
        const float v = 0.5f * (p[i] + xr[i]);
        buf[i] = v;
        s += v;
        ss += v * v;
    }
#pragma unroll
    for (int o2 = 16; o2 > 0; o2 >>= 1) {
        s  += __shfl_xor_sync(0xffffffffu, s, o2);
        ss += __shfl_xor_sync(0xffffffffu, ss, o2);
    }
    if ((tid & 31) == 0) { red[tid >> 5] = s; red[32 + (tid >> 5)] = ss; }
    __syncthreads();
    if (tid == 0) {
        float ts = 0.f, tss = 0.f;
        for (int i = 0; i < (int)(blockDim.x >> 5); i++) { ts += red[i]; tss += red[32 + i]; }
        const float mean = ts / (float)H_;
        const float var = tss / (float)H_ - mean * mean;
        stats[0] = mean;
        stats[1] = rsqrtf(var + 1e-6f);
    }
    __syncthreads();
    const float mean = stats[0], inv = stats[1];
    for (int i = tid; i < H_; i += blockDim.x) o[i] = (buf[i] - mean) * inv;
}

// ------------------------------- launcher ------------------------------------------
extern "C" void kernel_launch(void* const* d_in, const int* in_sizes, int n_in,
                              void* d_out, int out_size)
{
    const float* x  = (const float*)d_in[0];
    const float* Wq = (const float*)d_in[1];
    const float* bq = (const float*)d_in[2];
    const float* Wk = (const float*)d_in[3];
    const float* bk = (const float*)d_in[4];
    const float* Wv = (const float*)d_in[5];
    const float* bv = (const float*)d_in[6];
    const float* Wo = (const float*)d_in[7];
    const float* bo = (const float*)d_in[8];
    const float* Wg = (const float*)d_in[9];
    const float* bg = (const float*)d_in[10];
    const float* Wc = (const float*)d_in[11];
    const float* bc = (const float*)d_in[12];
    const float* Ws = (const float*)d_in[13];
    const float* bs = (const float*)d_in[14];
    float* out = (float*)d_out;

    bf16 *xh, *Q, *K, *V, *VT, *cmp, *Qc, *Kc, *Vc, *VcT, *P;
    bf16 *Qs, *Ks, *Vs, *VsT, *comp_g, *sel_g, *win_g;
    bf16 *WqT, *WkT, *WvT, *WcT, *WoT;
    float *S, *pre, *gates, *scores;
    int* idx;
    cudaGetSymbolAddress((void**)&xh, g_xh);
    cudaGetSymbolAddress((void**)&Q, g_Q);
    cudaGetSymbolAddress((void**)&K, g_Kb);
    cudaGetSymbolAddress((void**)&V, g_Vb);
    cudaGetSymbolAddress((void**)&VT, g_VT);
    cudaGetSymbolAddress((void**)&cmp, g_cmp);
    cudaGetSymbolAddress((void**)&Qc, g_Qc);
    cudaGetSymbolAddress((void**)&Kc, g_Kc);
    cudaGetSymbolAddress((void**)&Vc, g_Vc);
    cudaGetSymbolAddress((void**)&VcT, g_VcT);
    cudaGetSymbolAddress((void**)&S, g_S);
    cudaGetSymbolAddress((void**)&P, g_P);
    cudaGetSymbolAddress((void**)&comp_g, g_comp_g);
    cudaGetSymbolAddress((void**)&Qs, g_Qs);
    cudaGetSymbolAddress((void**)&Ks, g_Ks);
    cudaGetSymbolAddress((void**)&Vs, g_Vs);
    cudaGetSymbolAddress((void**)&VsT, g_VsT);
    cudaGetSymbolAddress((void**)&sel_g, g_sel_g);
    cudaGetSymbolAddress((void**)&win_g, g_win_g);
    cudaGetSymbolAddress((void**)&pre, g_pre);
    cudaGetSymbolAddress((void**)&gates, g_gates);
    cudaGetSymbolAddress((void**)&scores, g_scores);
    cudaGetSymbolAddress((void**)&idx, g_idx);
    cudaGetSymbolAddress((void**)&WqT, g_WqT);
    cudaGetSymbolAddress((void**)&WkT, g_WkT);
    cudaGetSymbolAddress((void**)&WvT, g_WvT);
    cudaGetSymbolAddress((void**)&WcT, g_WcT);
    cudaGetSymbolAddress((void**)&WoT, g_WoT);

    cudaFuncSetAttribute((const void*)gemm_bf<0, 0>, cudaFuncAttributeMaxDynamicSharedMemorySize, GEMM_SMEM);
    cudaFuncSetAttribute((const void*)gemm_bf<0, 1>, cudaFuncAttributeMaxDynamicSharedMemorySize, GEMM_SMEM);
    cudaFuncSetAttribute((const void*)gemm_bf<1, 0>, cudaFuncAttributeMaxDynamicSharedMemorySize, GEMM_SMEM);

    const int MT = B_ * L_;
    const dim3 tb(32, 8);

    gates_scores_kernel<<<MT / 8, 256>>>(x, Wg, bg, Ws, bs, gates, scores);

    cvt_kernel<<<(unsigned)(((ll)MT * H_ / 4 + 255) / 256), 256>>>(x, xh, (ll)MT * H_ / 4);
    transpose_cvt_kernel<<<dim3(H_ / 32, H_ / 32), tb>>>(Wq, WqT, H_, H_);
    transpose_cvt_kernel<<<dim3(H_ / 32, H_ / 32), tb>>>(Wk, WkT, H_, H_);
    transpose_cvt_kernel<<<dim3(H_ / 32, H_ / 32), tb>>>(Wv, WvT, H_, H_);
    transpose_cvt_kernel<<<dim3(H_ / 32, (4 * H_) / 32), tb>>>(Wc, WcT, 4 * H_, H_);
    transpose_cvt_kernel<<<dim3(H_ / 32, (3 * H_) / 32), tb>>>(Wo, WoT, 3 * H_, H_);

    // full-sequence QKV (bf16 out)
    {
        dim3 g(H_ / 128, MT / 128, 1);
        gemm_bf<1, 0><<<g, 256, GEMM_SMEM>>>(xh, WqT, bq, nullptr, 0, 0, Q, MT, H_, H_, 1.f, H_, H_, 0, 0, 1, 0, 0, 0);
        gemm_bf<1, 0><<<g, 256, GEMM_SMEM>>>(xh, WkT, bk, nullptr, 0, 0, K, MT, H_, H_, 1.f, H_, H_, 0, 0, 1, 0, 0, 0);
        gemm_bf<1, 0><<<g, 256, GEMM_SMEM>>>(xh, WvT, bv, nullptr, 0, 0, V, MT, H_, H_, 1.f, H_, H_, 0, 0, 1, 0, 0, 0);
    }
    transpose_bf_kernel<<<dim3(H_ / 32, L_ / 32, B_), tb>>>(V, VT, L_, H_);

    // compressed branch projections
    {
        dim3 g(H_ / 128, (B_ * LC_) / 128, 1);
        gemm_bf<1, 0><<<g, 256, GEMM_SMEM>>>(xh, WcT, bc, nullptr, 0, 0, cmp, B_ * LC_, H_, 4 * H_, 1.f, 4 * H_, 4 * H_, 0, 0, 1, 0, 0, 0);
        gemm_bf<1, 0><<<g, 256, GEMM_SMEM>>>(cmp, WqT, bq, nullptr, 0, 0, Qc, B_ * LC_, H_, H_, 1.f, H_, H_, 0, 0, 1, 0, 0, 0);
        gemm_bf<1, 0><<<g, 256, GEMM_SMEM>>>(cmp, WkT, bk, nullptr, 0, 0, Kc, B_ * LC_, H_, H_, 1.f, H_, H_, 0, 0, 1, 0, 0, 0);
        gemm_bf<1, 0><<<g, 256, GEMM_SMEM>>>(cmp, WvT, bv, nullptr, 0, 0, Vc, B_ * LC_, H_, H_, 1.f, H_, H_, 0, 0, 1, 0, 0, 0);
    }
    transpose_bf_kernel<<<dim3(H_ / 32, LC_ / 32, B_), tb>>>(Vc, VcT, LC_, H_);

    topk_kernel<<<B_, 512>>>(scores, idx);
    gather_kernel<<<dim3(KSEL_, B_), 128>>>(Q, K, V, idx, Qs, Ks, Vs);
    transpose_bf_kernel<<<dim3(H_ / 32, KSEL_ / 32, B_), tb>>>(Vs, VsT, KSEL_, H_);

    // ---- compressed attention: PV emits gated bf16 (gate 0) ----
    gemm_bf<0, 0><<<dim3(LC_ / 128, LC_ / 128, B_), 256, GEMM_SMEM>>>(
        Qc, Kc, nullptr, nullptr, 0, 0, S, LC_, LC_, H_, SCALE_, H_, H_,
        (ll)LC_ * H_, 0, 1, (ll)LC_ * H_, 0, (ll)LC_ * LC_);
    softmax_kernel<<<B_ * LC_, 256>>>(S, P, LC_);
    gemm_bf<1, 0><<<dim3(H_ / 128, LC_ / 128, B_), 256, GEMM_SMEM>>>(
        P, VcT, nullptr, gates + 0, (ll)L_ * 3, 0, comp_g, LC_, H_, LC_, 1.f, LC_, LC_,
        (ll)LC_ * LC_, 0, 1, (ll)H_ * LC_, 0, (ll)LC_ * H_);

    // ---- selected attention: PV emits gated bf16 (gate 1) ----
    gemm_bf<0, 0><<<dim3(KSEL_ / 128, KSEL_ / 128, B_), 256, GEMM_SMEM>>>(
        Qs, Ks, nullptr, nullptr, 0, 0, S, KSEL_, KSEL_, H_, SCALE_, H_, H_,
        (ll)KSEL_ * H_, 0, 1, (ll)KSEL_ * H_, 0, (ll)KSEL_ * KSEL_);
    softmax_kernel<<<B_ * KSEL_, 256>>>(S, P, KSEL_);
    gemm_bf<1, 0><<<dim3(H_ / 128, KSEL_ / 128, B_), 256, GEMM_SMEM>>>(
        P, VsT, nullptr, gates + 1, (ll)L_ * 3, 0, sel_g, KSEL_, H_, KSEL_, 1.f, KSEL_, KSEL_,
        (ll)KSEL_ * KSEL_, 0, 1, (ll)H_ * KSEL_, 0, (ll)KSEL_ * H_);

    // ---- window attention: PV emits gated bf16 (gate 2) ----
    gemm_bf<0, 0><<<dim3(WIN_ / 128, WIN_ / 128, B_ * NW_), 256, GEMM_SMEM>>>(
        Q, K, nullptr, nullptr, 0, 0, S, WIN_, WIN_, H_, SCALE_, H_, H_,
        (ll)L_ * H_, (ll)128 * H_, NW_,
        (ll)L_ * H_, (ll)128 * H_, (ll)WIN_ * WIN_);
    softmax_kernel<<<B_ * NW_ * WIN_, 256>>>(S, P, WIN_);
    gemm_bf<1, 0><<<dim3(H_ / 128, WIN_ / 128, B_ * NW_), 256, GEMM_SMEM>>>(
        P, VT, nullptr, gates + 2, (ll)L_ * 3, (ll)WIN_ * 3, win_g, WIN_, H_, WIN_, 1.f, WIN_, L_,
        (ll)NW_ * WIN_ * WIN_, (ll)WIN_ * WIN_, NW_,
        (ll)H_ * L_, 128, (ll)WIN_ * H_);

    // ---- split output projection: pre = win_g@Wo2^T + bo, += comp_g@Wo0^T, += sel_g@Wo1^T
    gemm_bf<0, 0><<<dim3(H_ / 128, MT / 128, 1), 256, GEMM_SMEM>>>(
        win_g, WoT + 2 * H_, bo, nullptr, 0, 0, pre, MT, H_, H_, 1.f, H_, 3 * H_, 0, 0, 1, 0, 0, 0);
    gemm_bf<0, 1><<<dim3(H_ / 128, LC_ / 128, B_), 256, GEMM_SMEM>>>(
        comp_g, WoT, nullptr, nullptr, 0, 0, pre, LC_, H_, H_, 1.f, H_, 3 * H_,
        (ll)LC_ * H_, 0, 1, 0, 0, (ll)L_ * H_);
    gemm_bf<0, 1><<<dim3(H_ / 128, KSEL_ / 128, B_), 256, GEMM_SMEM>>>(
        sel_g, WoT + H_, nullptr, nullptr, 0, 0, pre, KSEL_, H_, H_, 1.f, H_, 3 * H_,
        (ll)KSEL_ * H_, 0, 1, 0, 0, (ll)L_ * H_);

    final_ln_kernel<<<MT, 256>>>(pre, x, out);
}